// round 6
// baseline (speedup 1.0000x reference)
#include <cuda_runtime.h>

#define DN 200000
#define DDIM 256
#define DG 1024
#define DS 128
#define DM (DG*DS)

// ---------------- scratch: __device__ globals (no allocation allowed) --------
__device__ float g_q1[(size_t)DM*DDIM];
__device__ float g_k1[(size_t)DM*DDIM];
__device__ float g_v1[(size_t)DM*DDIM];
__device__ float g_att[(size_t)DM*DDIM];
__device__ float g_E[(size_t)DG*DS*DS];
__device__ float g_q2[(size_t)DN*DDIM];
__device__ float g_ks[(size_t)DN*DDIM];
__device__ float g_vs[(size_t)DN*DDIM];
__device__ float g_ko[(size_t)DM*DDIM];
__device__ float g_vo[(size_t)DM*DDIM];
__device__ float g_ss[DN];
__device__ float g_so[DM];
__device__ unsigned g_mx[DN];

// ---------------- packed f32x2 helpers (sm_103a FFMA2 path) ------------------
__device__ __forceinline__ unsigned long long pack2(float x, float y) {
    unsigned long long r;
    asm("mov.b64 %0, {%1,%2};" : "=l"(r)
        : "r"(__float_as_uint(x)), "r"(__float_as_uint(y)));
    return r;
}
__device__ __forceinline__ void fma2(unsigned long long& d,
                                     unsigned long long a, unsigned long long b) {
    asm("fma.rn.f32x2 %0, %1, %2, %0;" : "+l"(d) : "l"(a), "l"(b));
}
__device__ __forceinline__ float2 unpack2(unsigned long long r) {
    unsigned lo, hi;
    asm("mov.b64 {%0,%1}, %2;" : "=r"(lo), "=r"(hi) : "l"(r));
    return make_float2(__uint_as_float(lo), __uint_as_float(hi));
}
// monotonic float <-> uint for atomicMax over signed floats
__device__ __forceinline__ unsigned encf(float f) {
    unsigned u = __float_as_uint(f);
    return (u & 0x80000000u) ? ~u : (u | 0x80000000u);
}
__device__ __forceinline__ float decf(unsigned u) {
    return __uint_as_float((u & 0x80000000u) ? (u & 0x7fffffffu) : ~u);
}

// ---------------- GEMM + row-normalize: C[r,256] = proj(X[g?]@W^T) -----------
#define XSTR 68
#define WSTR 258

__global__ __launch_bounds__(256) void gemm_proj(
    const float* __restrict__ X, const int* __restrict__ gidx,
    const float* __restrict__ W, float* __restrict__ C)
{
    __shared__ float Xs[32 * XSTR];
    __shared__ float Ws[32 * WSTR];
    __shared__ int   rsrc[64];
    __shared__ float rn[64];

    int tid = threadIdx.x;
    int w = tid >> 5, lane = tid & 31;
    int r0 = blockIdx.x * 64;

    if (tid < 64) {
        rsrc[tid] = gidx ? gidx[r0 + tid] : (r0 + tid);
        rn[tid] = 0.f;
    }
    __syncthreads();

    unsigned long long acc[8][4];
#pragma unroll
    for (int i = 0; i < 8; i++) { acc[i][0]=0ULL; acc[i][1]=0ULL; acc[i][2]=0ULL; acc[i][3]=0ULL; }

    for (int k0 = 0; k0 < 256; k0 += 32) {
#pragma unroll
        for (int e = 0; e < 2; e++) {
            int idx = tid + e * 256;
            int row = idx >> 3, qq = idx & 7;
            float4 v = *(const float4*)(X + (size_t)rsrc[row] * 256 + (k0 + qq * 4));
            Xs[(qq*4+0)*XSTR + row] = v.x; Xs[(qq*4+1)*XSTR + row] = v.y;
            Xs[(qq*4+2)*XSTR + row] = v.z; Xs[(qq*4+3)*XSTR + row] = v.w;
        }
#pragma unroll
        for (int e = 0; e < 8; e++) {
            int idx = tid + e * 256;
            int col = idx >> 3, qq = idx & 7;
            float4 v = *(const float4*)(W + (size_t)col * 256 + (k0 + qq * 4));
            Ws[(qq*4+0)*WSTR + col] = v.x; Ws[(qq*4+1)*WSTR + col] = v.y;
            Ws[(qq*4+2)*WSTR + col] = v.z; Ws[(qq*4+3)*WSTR + col] = v.w;
        }
        __syncthreads();
#pragma unroll
        for (int kk = 0; kk < 32; kk++) {
            float4 xa = *(const float4*)(Xs + kk * XSTR + w * 8);
            float4 xb = *(const float4*)(Xs + kk * XSTR + w * 8 + 4);
            const unsigned long long* wp = (const unsigned long long*)(Ws + kk * WSTR);
            unsigned long long b0 = wp[lane*2],      b1 = wp[lane*2 + 1];
            unsigned long long b2 = wp[64 + lane*2], b3 = wp[64 + lane*2 + 1];
            float xs8[8] = {xa.x, xa.y, xa.z, xa.w, xb.x, xb.y, xb.z, xb.w};
#pragma unroll
            for (int i = 0; i < 8; i++) {
                unsigned long long a = pack2(xs8[i], xs8[i]);
                fma2(acc[i][0], a, b0); fma2(acc[i][1], a, b1);
                fma2(acc[i][2], a, b2); fma2(acc[i][3], a, b3);
            }
        }
        __syncthreads();
    }

    float2 p[8][4];
#pragma unroll
    for (int i = 0; i < 8; i++) {
        float ss = 0.f;
#pragma unroll
        for (int j = 0; j < 4; j++) {
            p[i][j] = unpack2(acc[i][j]);
            ss += p[i][j].x * p[i][j].x + p[i][j].y * p[i][j].y;
        }
        atomicAdd(&rn[w * 8 + i], ss);
    }
    __syncthreads();
#pragma unroll
    for (int i = 0; i < 8; i++) {
        float s = rsqrtf(rn[w * 8 + i]);
        size_t base = (size_t)(r0 + w * 8 + i) * 256;
        *(float4*)(C + base + lane * 4) =
            make_float4(p[i][0].x*s, p[i][0].y*s, p[i][1].x*s, p[i][1].y*s);
        *(float4*)(C + base + 128 + lane * 4) =
            make_float4(p[i][2].x*s, p[i][2].y*s, p[i][3].x*s, p[i][3].y*s);
    }
}

// -------- per-group scores: E = exp(Q@K^T - rowmax), one block per group ----
#define QSTR 132
#define KSTR 130

__global__ __launch_bounds__(256) void attn_scores(
    const float* __restrict__ Q, const float* __restrict__ K, float* __restrict__ E)
{
    __shared__ float Qs[32 * QSTR];
    __shared__ float Ks[32 * KSTR];
    __shared__ float pm[128 * 17];

    int tid = threadIdx.x;
    int w = tid >> 5, lane = tid & 31;
    int rg = w * 2 + (lane >> 4);       // 0..15, 8 rows each
    int lc = lane & 15;                 // cols {4lc..+3} U {64+4lc..+3}
    int g = blockIdx.x;
    const float* Qg = Q + (size_t)g * 128 * 256;
    const float* Kg = K + (size_t)g * 128 * 256;

    unsigned long long acc[8][4];
#pragma unroll
    for (int i = 0; i < 8; i++) { acc[i][0]=0ULL; acc[i][1]=0ULL; acc[i][2]=0ULL; acc[i][3]=0ULL; }

    for (int k0 = 0; k0 < 256; k0 += 32) {
#pragma unroll
        for (int e = 0; e < 4; e++) {
            int idx = tid + e * 256;
            int row = idx >> 3, qq = idx & 7;
            float4 v = *(const float4*)(Qg + (size_t)row * 256 + (k0 + qq * 4));
            Qs[(qq*4+0)*QSTR + row] = v.x; Qs[(qq*4+1)*QSTR + row] = v.y;
            Qs[(qq*4+2)*QSTR + row] = v.z; Qs[(qq*4+3)*QSTR + row] = v.w;
            float4 u = *(const float4*)(Kg + (size_t)row * 256 + (k0 + qq * 4));
            Ks[(qq*4+0)*KSTR + row] = u.x; Ks[(qq*4+1)*KSTR + row] = u.y;
            Ks[(qq*4+2)*KSTR + row] = u.z; Ks[(qq*4+3)*KSTR + row] = u.w;
        }
        __syncthreads();
#pragma unroll
        for (int kk = 0; kk < 32; kk++) {
            float4 xa = *(const float4*)(Qs + kk * QSTR + rg * 8);
            float4 xb = *(const float4*)(Qs + kk * QSTR + rg * 8 + 4);
            const unsigned long long* wp = (const unsigned long long*)(Ks + kk * KSTR);
            unsigned long long b0 = wp[lc*2],      b1 = wp[lc*2 + 1];
            unsigned long long b2 = wp[32 + lc*2], b3 = wp[32 + lc*2 + 1];
            float xs8[8] = {xa.x, xa.y, xa.z, xa.w, xb.x, xb.y, xb.z, xb.w};
#pragma unroll
            for (int i = 0; i < 8; i++) {
                unsigned long long a = pack2(xs8[i], xs8[i]);
                fma2(acc[i][0], a, b0); fma2(acc[i][1], a, b1);
                fma2(acc[i][2], a, b2); fma2(acc[i][3], a, b3);
            }
        }
        __syncthreads();
    }

    float c[8][8];
    int rb = rg * 8;
#pragma unroll
    for (int i = 0; i < 8; i++) {
        float2 p0 = unpack2(acc[i][0]), p1 = unpack2(acc[i][1]);
        float2 p2 = unpack2(acc[i][2]), p3 = unpack2(acc[i][3]);
        c[i][0]=p0.x; c[i][1]=p0.y; c[i][2]=p1.x; c[i][3]=p1.y;
        c[i][4]=p2.x; c[i][5]=p2.y; c[i][6]=p3.x; c[i][7]=p3.y;
        float m = c[i][0];
#pragma unroll
        for (int j = 1; j < 8; j++) m = fmaxf(m, c[i][j]);
        pm[(rb + i) * 17 + lc] = m;
    }
    __syncthreads();
#pragma unroll
    for (int i = 0; i < 8; i++) {
        float m = pm[(rb + i) * 17];
#pragma unroll
        for (int t = 1; t < 16; t++) m = fmaxf(m, pm[(rb + i) * 17 + t]);
        size_t base = (size_t)g * 16384 + (size_t)(rb + i) * 128;
        *(float4*)(E + base + lc * 4) = make_float4(
            __expf(c[i][0]-m), __expf(c[i][1]-m), __expf(c[i][2]-m), __expf(c[i][3]-m));
        *(float4*)(E + base + 64 + lc * 4) = make_float4(
            __expf(c[i][4]-m), __expf(c[i][5]-m), __expf(c[i][6]-m), __expf(c[i][7]-m));
    }
}

// -------- per-group apply: O_half = E @ V_half (no normalize needed) --------
#define ESTR 132
#define VSTR 132

__global__ __launch_bounds__(256) void attn_apply(
    const float* __restrict__ E, const float* __restrict__ V, float* __restrict__ O)
{
    __shared__ float Es[32 * ESTR];
    __shared__ float Vs[32 * VSTR];

    int tid = threadIdx.x;
    int w = tid >> 5, lane = tid & 31;
    int rg = w * 2 + (lane >> 4);
    int lc = lane & 15;
    int g = blockIdx.x >> 1, half = blockIdx.x & 1;
    const float* Eg = E + (size_t)g * 16384;
    const float* Vg = V + (size_t)g * 128 * 256 + half * 128;

    unsigned long long acc[8][4];
#pragma unroll
    for (int i = 0; i < 8; i++) { acc[i][0]=0ULL; acc[i][1]=0ULL; acc[i][2]=0ULL; acc[i][3]=0ULL; }

    for (int k0 = 0; k0 < 128; k0 += 32) {
#pragma unroll
        for (int e = 0; e < 4; e++) {
            int idx = tid + e * 256;
            int row = idx >> 3, qq = idx & 7;
            float4 v = *(const float4*)(Eg + (size_t)row * 128 + (k0 + qq * 4));
            Es[(qq*4+0)*ESTR + row] = v.x; Es[(qq*4+1)*ESTR + row] = v.y;
            Es[(qq*4+2)*ESTR + row] = v.z; Es[(qq*4+3)*ESTR + row] = v.w;
            int kk = idx >> 5, cv = idx & 31;
            float4 u = *(const float4*)(Vg + (size_t)(k0 + kk) * 256 + cv * 4);
            *(float4*)(Vs + kk * VSTR + cv * 4) = u;
        }
        __syncthreads();
#pragma unroll
        for (int kk = 0; kk < 32; kk++) {
            float4 xa = *(const float4*)(Es + kk * ESTR + rg * 8);
            float4 xb = *(const float4*)(Es + kk * ESTR + rg * 8 + 4);
            const unsigned long long* wp = (const unsigned long long*)(Vs + kk * VSTR);
            unsigned long long b0 = wp[lc*2],      b1 = wp[lc*2 + 1];
            unsigned long long b2 = wp[32 + lc*2], b3 = wp[32 + lc*2 + 1];
            float xs8[8] = {xa.x, xa.y, xa.z, xa.w, xb.x, xb.y, xb.z, xb.w};
#pragma unroll
            for (int i = 0; i < 8; i++) {
                unsigned long long a = pack2(xs8[i], xs8[i]);
                fma2(acc[i][0], a, b0); fma2(acc[i][1], a, b1);
                fma2(acc[i][2], a, b2); fma2(acc[i][3], a, b3);
            }
        }
        __syncthreads();
    }

    int rb = rg * 8;
#pragma unroll
    for (int i = 0; i < 8; i++) {
        float2 p0 = unpack2(acc[i][0]), p1 = unpack2(acc[i][1]);
        float2 p2 = unpack2(acc[i][2]), p3 = unpack2(acc[i][3]);
        size_t base = (size_t)(g * 128 + rb + i) * 256 + half * 128;
        *(float4*)(O + base + lc * 4)      = make_float4(p0.x, p0.y, p1.x, p1.y);
        *(float4*)(O + base + 64 + lc * 4) = make_float4(p2.x, p2.y, p3.x, p3.y);
    }
}

// ---------------- small kernels ---------------------------------------------
__global__ void rowdot(const float* __restrict__ A, const float* __restrict__ B,
                       const int* __restrict__ ga, float* __restrict__ out, int nrows)
{
    int row = blockIdx.x * 8 + (threadIdx.x >> 5);
    int lane = threadIdx.x & 31;
    if (row >= nrows) return;
    int ra = ga ? ga[row] : row;
    const float4* a = (const float4*)(A + (size_t)ra * 256);
    const float4* b = (const float4*)(B + (size_t)row * 256);
    float4 a0 = a[lane], b0 = b[lane], a1 = a[lane + 32], b1 = b[lane + 32];
    float s = a0.x*b0.x + a0.y*b0.y + a0.z*b0.z + a0.w*b0.w
            + a1.x*b1.x + a1.y*b1.y + a1.z*b1.z + a1.w*b1.w;
#pragma unroll
    for (int o = 16; o; o >>= 1) s += __shfl_xor_sync(0xffffffffu, s, o);
    if (lane == 0) out[row] = s;
}

__global__ void kinit_max(const float* __restrict__ ss, unsigned* __restrict__ mx, int n)
{
    int i = blockIdx.x * 256 + threadIdx.x;
    if (i < n) mx[i] = encf(ss[i]);
}

__global__ void kseg_max(const float* __restrict__ so, const int* __restrict__ seg,
                         unsigned* __restrict__ mx)
{
    int i = blockIdx.x * 256 + threadIdx.x;
    atomicMax(&mx[seg[i]], encf(so[i]));
}

__global__ void kout_init(const float* __restrict__ ss, const unsigned* __restrict__ mx,
                          const float* __restrict__ vs, float* __restrict__ out)
{
    int t = blockIdx.x * 256 + threadIdx.x;
    int i = t >> 6, j = t & 63;
    float e = __expf(ss[i] - decf(mx[i]));
    float4 v = ((const float4*)vs)[(size_t)i * 64 + j];
    ((float4*)out)[(size_t)i * 64 + j] = make_float4(e*v.x, e*v.y, e*v.z, e*v.w);
}

__global__ void kocc_acc(const float* __restrict__ so, const int* __restrict__ seg,
                         const unsigned* __restrict__ mx, const float* __restrict__ vo,
                         float* __restrict__ out)
{
    int t = blockIdx.x * 256 + threadIdx.x;
    int i = t >> 6, j = t & 63;
    int n = seg[i];
    float e = __expf(so[i] - decf(mx[n]));
    float4 v = ((const float4*)vo)[(size_t)i * 64 + j];
    float* p = out + (size_t)n * 256 + j * 4;
    atomicAdd(p + 0, e * v.x); atomicAdd(p + 1, e * v.y);
    atomicAdd(p + 2, e * v.z); atomicAdd(p + 3, e * v.w);
}

__global__ void knorm(float* __restrict__ out)
{
    int row = blockIdx.x * 8 + (threadIdx.x >> 5);
    int lane = threadIdx.x & 31;
    float4* p = (float4*)(out + (size_t)row * 256);
    float4 a = p[lane], b = p[lane + 32];
    float s = a.x*a.x + a.y*a.y + a.z*a.z + a.w*a.w
            + b.x*b.x + b.y*b.y + b.z*b.z + b.w*b.w;
#pragma unroll
    for (int o = 16; o; o >>= 1) s += __shfl_xor_sync(0xffffffffu, s, o);
    float r = rsqrtf(s);
    p[lane]      = make_float4(a.x*r, a.y*r, a.z*r, a.w*r);
    p[lane + 32] = make_float4(b.x*r, b.y*r, b.z*r, b.w*r);
}

// ---------------- launch -----------------------------------------------------
extern "C" void kernel_launch(void* const* d_in, const int* in_sizes, int n_in,
                              void* d_out, int out_size)
{
    const float* xS  = (const float*)d_in[0];
    const int*   sub = (const int*)  d_in[1];
    const float* Wq1 = (const float*)d_in[2];
    const float* Wk1 = (const float*)d_in[3];
    const float* Wv1 = (const float*)d_in[4];
    const float* Wq2 = (const float*)d_in[5];
    const float* Wk2 = (const float*)d_in[6];
    const float* Wv2 = (const float*)d_in[7];
    float* out = (float*)d_out;

    float *q1, *k1, *v1, *att, *E, *q2, *ks, *vs, *ko, *vo, *ss, *so;
    unsigned* mx;
    cudaGetSymbolAddress((void**)&q1,  g_q1);
    cudaGetSymbolAddress((void**)&k1,  g_k1);
    cudaGetSymbolAddress((void**)&v1,  g_v1);
    cudaGetSymbolAddress((void**)&att, g_att);
    cudaGetSymbolAddress((void**)&E,   g_E);
    cudaGetSymbolAddress((void**)&q2,  g_q2);
    cudaGetSymbolAddress((void**)&ks,  g_ks);
    cudaGetSymbolAddress((void**)&vs,  g_vs);
    cudaGetSymbolAddress((void**)&ko,  g_ko);
    cudaGetSymbolAddress((void**)&vo,  g_vo);
    cudaGetSymbolAddress((void**)&ss,  g_ss);
    cudaGetSymbolAddress((void**)&so,  g_so);
    cudaGetSymbolAddress((void**)&mx,  g_mx);

    // ---- phase 1: subset attention ----
    gemm_proj<<<DM / 64, 256>>>(xS, sub, Wq1, q1);
    gemm_proj<<<DM / 64, 256>>>(xS, sub, Wk1, k1);
    gemm_proj<<<DM / 64, 256>>>(xS, sub, Wv1, v1);
    attn_scores<<<DG, 256>>>(q1, k1, E);
    attn_apply<<<DG * 2, 256>>>(E, v1, att);

    // ---- phase 2: projections ----
    gemm_proj<<<DM / 64, 256>>>(att, nullptr, Wk2, ko);
    gemm_proj<<<DM / 64, 256>>>(att, nullptr, Wv2, vo);
    gemm_proj<<<DN / 64, 256>>>(xS, nullptr, Wq2, q2);
    gemm_proj<<<DN / 64, 256>>>(xS, nullptr, Wk2, ks);
    gemm_proj<<<DN / 64, 256>>>(xS, nullptr, Wv2, vs);

    // ---- phase 2: segment softmax aggregation ----
    rowdot<<<DN / 8, 256>>>(q2, ks, nullptr, ss, DN);
    rowdot<<<DM / 8, 256>>>(q2, ko, sub, so, DM);
    kinit_max<<<(DN + 255) / 256, 256>>>(ss, mx, DN);
    kseg_max<<<DM / 256, 256>>>(so, sub, mx);
    kout_init<<<DN * 64 / 256, 256>>>(ss, mx, vs, out);
    kocc_acc<<<DM * 64 / 256, 256>>>(so, sub, mx, vo, out);
    knorm<<<DN / 8, 256>>>(out);
}

// round 10
// speedup vs baseline: 1.7250x; 1.7250x over previous
#include <cuda_runtime.h>
#include <cuda_bf16.h>
#include <cstdint>

#define DN 200000
#define DDIM 256
#define DG 1024
#define DS 128
#define DM (DG*DS)

typedef __nv_bfloat16 bf16;

// ---------------- scratch: __device__ globals (no allocation allowed) --------
__device__ float          g_q1[(size_t)DM*DDIM];
__device__ float          g_k1[(size_t)DM*DDIM];
__device__ float          g_v1[(size_t)DM*DDIM];
__device__ float          g_E [(size_t)DG*DS*DS];
__device__ unsigned short g_ath[(size_t)DM*DDIM];   // att hi (bf16 bits)
__device__ unsigned short g_atl[(size_t)DM*DDIM];   // att lo
__device__ unsigned short g_xh [(size_t)DN*DDIM];   // xS hi
__device__ unsigned short g_xl [(size_t)DN*DDIM];   // xS lo
__device__ unsigned short g_wh [6*65536];           // weights hi
__device__ unsigned short g_wl [6*65536];           // weights lo
__device__ float          g_q2[(size_t)DN*DDIM];
__device__ float          g_ks[(size_t)DN*DDIM];
__device__ float          g_vs[(size_t)DN*DDIM];
__device__ float          g_ko[(size_t)DM*DDIM];
__device__ float          g_vo[(size_t)DM*DDIM];
__device__ float          g_ss[DN];
__device__ float          g_so[DM];
__device__ unsigned       g_mx[DN];

// ---------------- fp32 -> (hi,lo) bf16 split ---------------------------------
__device__ __forceinline__ void split_wr(bf16* H, bf16* L, float4 v) {
    bf16 h0 = __float2bfloat16(v.x), h1 = __float2bfloat16(v.y);
    bf16 h2 = __float2bfloat16(v.z), h3 = __float2bfloat16(v.w);
    bf16 l0 = __float2bfloat16(v.x - __bfloat162float(h0));
    bf16 l1 = __float2bfloat16(v.y - __bfloat162float(h1));
    bf16 l2 = __float2bfloat16(v.z - __bfloat162float(h2));
    bf16 l3 = __float2bfloat16(v.w - __bfloat162float(h3));
    ((__nv_bfloat162*)H)[0] = __halves2bfloat162(h0, h1);
    ((__nv_bfloat162*)H)[1] = __halves2bfloat162(h2, h3);
    ((__nv_bfloat162*)L)[0] = __halves2bfloat162(l0, l1);
    ((__nv_bfloat162*)L)[1] = __halves2bfloat162(l2, l3);
}

__global__ void ksplit(const float* __restrict__ x, bf16* __restrict__ hi,
                       bf16* __restrict__ lo, int n4) {
    int i = blockIdx.x * 256 + threadIdx.x;
    if (i < n4)
        split_wr(hi + 4 * (size_t)i, lo + 4 * (size_t)i, ((const float4*)x)[i]);
}

// ---------------- mma.sync bf16 GEMM + proj: C[128,256] = proj(X@W^T) --------
// 3-term split: Ahi*Bhi + Ahi*Blo + Alo*Bhi (fp32 accumulate).
// Block 512 thr (16 warps), tile M=128 N=256, K chunks of 32.
// warp grid: wm = wid&1 (M, 2x64), wn = wid>>1 (N, 8x32).
__device__ __forceinline__ void mma16816(float* d, const unsigned* a,
                                         unsigned b0, unsigned b1) {
    asm volatile(
        "mma.sync.aligned.m16n8k16.row.col.f32.bf16.bf16.f32 "
        "{%0,%1,%2,%3}, {%4,%5,%6,%7}, {%8,%9}, {%0,%1,%2,%3};"
        : "+f"(d[0]), "+f"(d[1]), "+f"(d[2]), "+f"(d[3])
        : "r"(a[0]), "r"(a[1]), "r"(a[2]), "r"(a[3]), "r"(b0), "r"(b1));
}

#define ASTR 56     // b16 stride (32 cols + 24 pad): 112B, conflict-free frags
#define OFF_AH 0
#define OFF_AL 14336
#define OFF_BH 28672
#define OFF_BL 57344
#define OFF_RN 86016
#define OFF_RS 86528
#define SMEMTC 87040

__global__ void __launch_bounds__(512) mma_proj_tc(
    const bf16* __restrict__ Ahi, const bf16* __restrict__ Alo,
    const int* __restrict__ gidx,
    const bf16* __restrict__ Bhi, const bf16* __restrict__ Blo,
    float* __restrict__ C, int nrows)
{
    extern __shared__ __align__(16) char smc[];
    bf16*  AsH  = (bf16*)(smc + OFF_AH);
    bf16*  AsL  = (bf16*)(smc + OFF_AL);
    bf16*  BsH  = (bf16*)(smc + OFF_BH);
    bf16*  BsL  = (bf16*)(smc + OFF_BL);
    float* rn   = (float*)(smc + OFF_RN);
    int*   rsrc = (int*)  (smc + OFF_RS);

    int tid = threadIdx.x;
    int wid = tid >> 5, lane = tid & 31;
    int wm = wid & 1, wn = wid >> 1;
    int r0 = blockIdx.x * 128;

    if (tid < 128) {
        int sr = r0 + tid;
        if (sr >= nrows) sr = nrows - 1;
        rsrc[tid] = gidx ? gidx[sr] : sr;
        rn[tid] = 0.f;
    }
    __syncthreads();

    float acc[4][4][4];
#pragma unroll
    for (int mt = 0; mt < 4; mt++)
#pragma unroll
        for (int nt = 0; nt < 4; nt++)
#pragma unroll
            for (int j = 0; j < 4; j++) acc[mt][nt][j] = 0.f;

    int frow = tid >> 2;          // 0..127 (fill row)
    int fcg  = tid & 3;           // col group of 8
    size_t asrc = (size_t)rsrc[frow] * 256;
    int g  = lane >> 2;           // frag group (row/col 0..7)
    int tg = lane & 3;            // thread-in-group

    for (int c = 0; c < 8; c++) {
        int k0 = c * 32;
        // fill A: 128 x 32 (hi + lo)
        {
            uint4 vh = *(const uint4*)(Ahi + asrc + k0 + fcg * 8);
            uint4 vl = *(const uint4*)(Alo + asrc + k0 + fcg * 8);
            *(uint4*)(AsH + frow * ASTR + fcg * 8) = vh;
            *(uint4*)(AsL + frow * ASTR + fcg * 8) = vl;
        }
        // fill B: 256 x 32 (hi + lo)
#pragma unroll
        for (int rr = 0; rr < 2; rr++) {
            int n = frow + rr * 128;
            uint4 vh = *(const uint4*)(Bhi + (size_t)n * 256 + k0 + fcg * 8);
            uint4 vl = *(const uint4*)(Blo + (size_t)n * 256 + k0 + fcg * 8);
            *(uint4*)(BsH + n * ASTR + fcg * 8) = vh;
            *(uint4*)(BsL + n * ASTR + fcg * 8) = vl;
        }
        __syncthreads();

#pragma unroll
        for (int ks = 0; ks < 2; ks++) {
            int ko = ks * 16;
#pragma unroll
            for (int term = 0; term < 3; term++) {
                const bf16* At = (term == 2) ? AsL : AsH;
                const bf16* Bt = (term == 1) ? BsL : BsH;
                unsigned a[4][4];
#pragma unroll
                for (int mt = 0; mt < 4; mt++) {
                    const bf16* p = At + (wm * 64 + mt * 16 + g) * ASTR + ko + tg * 2;
                    a[mt][0] = *(const unsigned*)(p);
                    a[mt][1] = *(const unsigned*)(p + 8 * ASTR);
                    a[mt][2] = *(const unsigned*)(p + 8);
                    a[mt][3] = *(const unsigned*)(p + 8 * ASTR + 8);
                }
#pragma unroll
                for (int nt = 0; nt < 4; nt++) {
                    const bf16* p = Bt + (wn * 32 + nt * 8 + g) * ASTR + ko + tg * 2;
                    unsigned b0 = *(const unsigned*)(p);
                    unsigned b1 = *(const unsigned*)(p + 8);
#pragma unroll
                    for (int mt = 0; mt < 4; mt++)
                        mma16816(acc[mt][nt], a[mt], b0, b1);
                }
            }
        }
        __syncthreads();
    }

    // row sumsq (projection) across the full 256 cols: smem atomics
#pragma unroll
    for (int mt = 0; mt < 4; mt++) {
        float s0 = 0.f, s1 = 0.f;
#pragma unroll
        for (int nt = 0; nt < 4; nt++) {
            s0 += acc[mt][nt][0] * acc[mt][nt][0] + acc[mt][nt][1] * acc[mt][nt][1];
            s1 += acc[mt][nt][2] * acc[mt][nt][2] + acc[mt][nt][3] * acc[mt][nt][3];
        }
        s0 += __shfl_xor_sync(0xffffffffu, s0, 1);
        s0 += __shfl_xor_sync(0xffffffffu, s0, 2);
        s1 += __shfl_xor_sync(0xffffffffu, s1, 1);
        s1 += __shfl_xor_sync(0xffffffffu, s1, 2);
        if (tg == 0) {
            atomicAdd(&rn[wm * 64 + mt * 16 + g], s0);
            atomicAdd(&rn[wm * 64 + mt * 16 + 8 + g], s1);
        }
    }
    __syncthreads();

#pragma unroll
    for (int mt = 0; mt < 4; mt++) {
        int rl = wm * 64 + mt * 16 + g;
        float sa = rsqrtf(rn[rl]);
        float sb = rsqrtf(rn[rl + 8]);
        bool oka = (r0 + rl) < nrows;
        bool okb = (r0 + rl + 8) < nrows;
        float* ca = C + (size_t)(r0 + rl) * 256;
        float* cb = C + (size_t)(r0 + rl + 8) * 256;
#pragma unroll
        for (int nt = 0; nt < 4; nt++) {
            int col = wn * 32 + nt * 8 + tg * 2;
            if (oka) *(float2*)(ca + col) =
                make_float2(acc[mt][nt][0] * sa, acc[mt][nt][1] * sa);
            if (okb) *(float2*)(cb + col) =
                make_float2(acc[mt][nt][2] * sb, acc[mt][nt][3] * sb);
        }
    }
}

// ---------------- packed f32x2 helpers (FFMA2 path, attention) ---------------
__device__ __forceinline__ unsigned long long pack2(float x, float y) {
    unsigned long long r;
    asm("mov.b64 %0, {%1,%2};" : "=l"(r)
        : "r"(__float_as_uint(x)), "r"(__float_as_uint(y)));
    return r;
}
__device__ __forceinline__ void fma2(unsigned long long& d,
                                     unsigned long long a, unsigned long long b) {
    asm("fma.rn.f32x2 %0, %1, %2, %0;" : "+l"(d) : "l"(a), "l"(b));
}
__device__ __forceinline__ float2 unpack2(unsigned long long r) {
    unsigned lo, hi;
    asm("mov.b64 {%0,%1}, %2;" : "=r"(lo), "=r"(hi) : "l"(r));
    return make_float2(__uint_as_float(lo), __uint_as_float(hi));
}
__device__ __forceinline__ unsigned encf(float f) {
    unsigned u = __float_as_uint(f);
    return (u & 0x80000000u) ? ~u : (u | 0x80000000u);
}
__device__ __forceinline__ float decf(unsigned u) {
    return __uint_as_float((u & 0x80000000u) ? (u & 0x7fffffffu) : ~u);
}

// -------- per-group scores: E = exp(Q@K^T - rowmax) --------------------------
#define QSTR 132
#define KSTR 130

__global__ __launch_bounds__(256) void attn_scores(
    const float* __restrict__ Q, const float* __restrict__ K, float* __restrict__ E)
{
    __shared__ float Qs[32 * QSTR];
    __shared__ float Ks[32 * KSTR];
    __shared__ float pm[128 * 17];

    int tid = threadIdx.x;
    int lane = tid & 31;
    int w = tid >> 5;
    int rg = w * 2 + (lane >> 4);
    int lc = lane & 15;
    int g = blockIdx.x;
    const float* Qg = Q + (size_t)g * 128 * 256;
    const float* Kg = K + (size_t)g * 128 * 256;

    unsigned long long acc[8][4];
#pragma unroll
    for (int i = 0; i < 8; i++) { acc[i][0]=0ULL; acc[i][1]=0ULL; acc[i][2]=0ULL; acc[i][3]=0ULL; }

    for (int k0 = 0; k0 < 256; k0 += 32) {
#pragma unroll
        for (int e = 0; e < 4; e++) {
            int idx = tid + e * 256;
            int row = idx >> 3, qq = idx & 7;
            float4 v = *(const float4*)(Qg + (size_t)row * 256 + (k0 + qq * 4));
            Qs[(qq*4+0)*QSTR + row] = v.x; Qs[(qq*4+1)*QSTR + row] = v.y;
            Qs[(qq*4+2)*QSTR + row] = v.z; Qs[(qq*4+3)*QSTR + row] = v.w;
            float4 u = *(const float4*)(Kg + (size_t)row * 256 + (k0 + qq * 4));
            Ks[(qq*4+0)*KSTR + row] = u.x; Ks[(qq*4+1)*KSTR + row] = u.y;
            Ks[(qq*4+2)*KSTR + row] = u.z; Ks[(qq*4+3)*KSTR + row] = u.w;
        }
        __syncthreads();
#pragma unroll
        for (int kk = 0; kk < 32; kk++) {
            float4 xa = *(const float4*)(Qs + kk * QSTR + rg * 8);
            float4 xb = *(const float4*)(Qs + kk * QSTR + rg * 8 + 4);
            const unsigned long long* wp = (const unsigned long long*)(Ks + kk * KSTR);
            unsigned long long b0 = wp[lc*2],      b1 = wp[lc*2 + 1];
            unsigned long long b2 = wp[32 + lc*2], b3 = wp[32 + lc*2 + 1];
            float xs8[8] = {xa.x, xa.y, xa.z, xa.w, xb.x, xb.y, xb.z, xb.w};
#pragma unroll
            for (int i = 0; i < 8; i++) {
                unsigned long long a = pack2(xs8[i], xs8[i]);
                fma2(acc[i][0], a, b0); fma2(acc[i][1], a, b1);
                fma2(acc[i][2], a, b2); fma2(acc[i][3], a, b3);
            }
        }
        __syncthreads();
    }

    float c[8][8];
    int rb = rg * 8;
#pragma unroll
    for (int i = 0; i < 8; i++) {
        float2 p0 = unpack2(acc[i][0]), p1 = unpack2(acc[i][1]);
        float2 p2 = unpack2(acc[i][2]), p3 = unpack2(acc[i][3]);
        c[i][0]=p0.x; c[i][1]=p0.y; c[i][2]=p1.x; c[i][3]=p1.y;
        c[i][4]=p2.x; c[i][5]=p2.y; c[i][6]=p3.x; c[i][7]=p3.y;
        float m = c[i][0];
#pragma unroll
        for (int j = 1; j < 8; j++) m = fmaxf(m, c[i][j]);
        pm[(rb + i) * 17 + lc] = m;
    }
    __syncthreads();
#pragma unroll
    for (int i = 0; i < 8; i++) {
        float m = pm[(rb + i) * 17];
#pragma unroll
        for (int t = 1; t < 16; t++) m = fmaxf(m, pm[(rb + i) * 17 + t]);
        size_t base = (size_t)g * 16384 + (size_t)(rb + i) * 128;
        *(float4*)(E + base + lc * 4) = make_float4(
            __expf(c[i][0]-m), __expf(c[i][1]-m), __expf(c[i][2]-m), __expf(c[i][3]-m));
        *(float4*)(E + base + 64 + lc * 4) = make_float4(
            __expf(c[i][4]-m), __expf(c[i][5]-m), __expf(c[i][6]-m), __expf(c[i][7]-m));
    }
}

// -------- per-group apply: att_half = E @ V_half -> split bf16 out -----------
#define ESTR 132
#define VSTR 132

__global__ __launch_bounds__(256) void attn_apply(
    const float* __restrict__ E, const float* __restrict__ V,
    bf16* __restrict__ Oh, bf16* __restrict__ Ol)
{
    __shared__ float Es[32 * ESTR];
    __shared__ float Vs[32 * VSTR];

    int tid = threadIdx.x;
    int lane = tid & 31;
    int w = tid >> 5;
    int rg = w * 2 + (lane >> 4);
    int lc = lane & 15;
    int g = blockIdx.x >> 1, half = blockIdx.x & 1;
    const float* Eg = E + (size_t)g * 16384;
    const float* Vg = V + (size_t)g * 128 * 256 + half * 128;

    unsigned long long acc[8][4];
#pragma unroll
    for (int i = 0; i < 8; i++) { acc[i][0]=0ULL; acc[i][1]=0ULL; acc[i][2]=0ULL; acc[i][3]=0ULL; }

    for (int k0 = 0; k0 < 128; k0 += 32) {
#pragma unroll
        for (int e = 0; e < 4; e++) {
            int idx = tid + e * 256;
            int row = idx >> 3, qq = idx & 7;
            float4 v = *(const float4*)(Eg + (size_t)row * 128 + (k0 + qq * 4));
            Es[(qq*4+0)*ESTR + row] = v.x; Es[(qq*4+1)*ESTR + row] = v.y;
            Es[(qq*4+2)*ESTR + row] = v.z; Es[(qq*4+3)*ESTR + row] = v.w;
            int kk = idx >> 5, cv = idx & 31;
            float4 u = *(const float4*)(Vg + (size_t)(k0 + kk) * 256 + cv * 4);
            *(float4*)(Vs + kk * VSTR + cv * 4) = u;
        }
        __syncthreads();
#pragma unroll
        for (int kk = 0; kk < 32; kk++) {
            float4 xa = *(const float4*)(Es + kk * ESTR + rg * 8);
            float4 xb = *(const float4*)(Es + kk * ESTR + rg * 8 + 4);
            const unsigned long long* wp = (const unsigned long long*)(Vs + kk * VSTR);
            unsigned long long b0 = wp[lc*2],      b1 = wp[lc*2 + 1];
            unsigned long long b2 = wp[32 + lc*2], b3 = wp[32 + lc*2 + 1];
            float xs8[8] = {xa.x, xa.y, xa.z, xa.w, xb.x, xb.y, xb.z, xb.w};
#pragma unroll
            for (int i = 0; i < 8; i++) {
                unsigned long long a = pack2(xs8[i], xs8[i]);
                fma2(acc[i][0], a, b0); fma2(acc[i][1], a, b1);
                fma2(acc[i][2], a, b2); fma2(acc[i][3], a, b3);
            }
        }
        __syncthreads();
    }

    int rb = rg * 8;
#pragma unroll
    for (int i = 0; i < 8; i++) {
        float2 p0 = unpack2(acc[i][0]), p1 = unpack2(acc[i][1]);
        float2 p2 = unpack2(acc[i][2]), p3 = unpack2(acc[i][3]);
        size_t base = (size_t)(g * 128 + rb + i) * 256 + half * 128;
        split_wr(Oh + base + lc * 4,      Ol + base + lc * 4,
                 make_float4(p0.x, p0.y, p1.x, p1.y));
        split_wr(Oh + base + 64 + lc * 4, Ol + base + 64 + lc * 4,
                 make_float4(p2.x, p2.y, p3.x, p3.y));
    }
}

// ---------------- segment phase ---------------------------------------------
__global__ void rowdot(const float* __restrict__ A, const float* __restrict__ B,
                       const int* __restrict__ ga, float* __restrict__ out, int nrows)
{
    int row = blockIdx.x * 8 + (threadIdx.x >> 5);
    int lane = threadIdx.x & 31;
    if (row >= nrows) return;
    int ra = ga ? ga[row] : row;
    const float4* a = (const float4*)(A + (size_t)ra * 256);
    const float4* b = (const float4*)(B + (size_t)row * 256);
    float4 a0 = a[lane], b0 = b[lane], a1 = a[lane + 32], b1 = b[lane + 32];
    float s = a0.x*b0.x + a0.y*b0.y + a0.z*b0.z + a0.w*b0.w
            + a1.x*b1.x + a1.y*b1.y + a1.z*b1.z + a1.w*b1.w;
#pragma unroll
    for (int o = 16; o; o >>= 1) s += __shfl_xor_sync(0xffffffffu, s, o);
    if (lane == 0) out[row] = s;
}

__global__ void kinit_max(const float* __restrict__ ss, unsigned* __restrict__ mx, int n)
{
    int i = blockIdx.x * 256 + threadIdx.x;
    if (i < n) mx[i] = encf(ss[i]);
}

__global__ void kseg_max(const float* __restrict__ so, const int* __restrict__ seg,
                         unsigned* __restrict__ mx)
{
    int i = blockIdx.x * 256 + threadIdx.x;
    atomicMax(&mx[seg[i]], encf(so[i]));
}

__global__ void kout_init(const float* __restrict__ ss, const unsigned* __restrict__ mx,
                          const float* __restrict__ vs, float* __restrict__ out)
{
    int t = blockIdx.x * 256 + threadIdx.x;
    int i = t >> 6, j = t & 63;
    float e = __expf(ss[i] - decf(mx[i]));
    float4 v = ((const float4*)vs)[(size_t)i * 64 + j];
    ((float4*)out)[(size_t)i * 64 + j] = make_float4(e*v.x, e*v.y, e*v.z, e*v.w);
}

__global__ void kocc_acc(const float* __restrict__ so, const int* __restrict__ seg,
                         const unsigned* __restrict__ mx, const float* __restrict__ vo,
                         float* __restrict__ out)
{
    int t = blockIdx.x * 256 + threadIdx.x;
    int i = t >> 6, j = t & 63;
    int n = seg[i];
    float e = __expf(so[i] - decf(mx[n]));
    float4 v = ((const float4*)vo)[(size_t)i * 64 + j];
    float* p = out + (size_t)n * 256 + j * 4;
    atomicAdd(p + 0, e * v.x); atomicAdd(p + 1, e * v.y);
    atomicAdd(p + 2, e * v.z); atomicAdd(p + 3, e * v.w);
}

__global__ void knorm(float* __restrict__ out)
{
    int row = blockIdx.x * 8 + (threadIdx.x >> 5);
    int lane = threadIdx.x & 31;
    float4* p = (float4*)(out + (size_t)row * 256);
    float4 a = p[lane], b = p[lane + 32];
    float s = a.x*a.x + a.y*a.y + a.z*a.z + a.w*a.w
            + b.x*b.x + b.y*b.y + b.z*b.z + b.w*b.w;
#pragma unroll
    for (int o = 16; o; o >>= 1) s += __shfl_xor_sync(0xffffffffu, s, o);
    float r = rsqrtf(s);
    p[lane]      = make_float4(a.x*r, a.y*r, a.z*r, a.w*r);
    p[lane + 32] = make_float4(b.x*r, b.y*r, b.z*r, b.w*r);
}

// ---------------- launch -----------------------------------------------------
extern "C" void kernel_launch(void* const* d_in, const int* in_sizes, int n_in,
                              void* d_out, int out_size)
{
    const float* xS  = (const float*)d_in[0];
    const int*   sub = (const int*)  d_in[1];
    const float* Wref[6] = { (const float*)d_in[2], (const float*)d_in[3],
                             (const float*)d_in[4], (const float*)d_in[5],
                             (const float*)d_in[6], (const float*)d_in[7] };
    float* out = (float*)d_out;

    float *q1, *k1, *v1, *E, *q2, *ks, *vs, *ko, *vo, *ss, *so;
    unsigned short *ath, *atl, *xh, *xl, *wh, *wl;
    unsigned* mx;
    cudaGetSymbolAddress((void**)&q1,  g_q1);
    cudaGetSymbolAddress((void**)&k1,  g_k1);
    cudaGetSymbolAddress((void**)&v1,  g_v1);
    cudaGetSymbolAddress((void**)&E,   g_E);
    cudaGetSymbolAddress((void**)&ath, g_ath);
    cudaGetSymbolAddress((void**)&atl, g_atl);
    cudaGetSymbolAddress((void**)&xh,  g_xh);
    cudaGetSymbolAddress((void**)&xl,  g_xl);
    cudaGetSymbolAddress((void**)&wh,  g_wh);
    cudaGetSymbolAddress((void**)&wl,  g_wl);
    cudaGetSymbolAddress((void**)&q2,  g_q2);
    cudaGetSymbolAddress((void**)&ks,  g_ks);
    cudaGetSymbolAddress((void**)&vs,  g_vs);
    cudaGetSymbolAddress((void**)&ko,  g_ko);
    cudaGetSymbolAddress((void**)&vo,  g_vo);
    cudaGetSymbolAddress((void**)&ss,  g_ss);
    cudaGetSymbolAddress((void**)&so,  g_so);
    cudaGetSymbolAddress((void**)&mx,  g_mx);

    // idempotent, not a stream op — safe under graph capture
    cudaFuncSetAttribute(mma_proj_tc, cudaFuncAttributeMaxDynamicSharedMemorySize, SMEMTC);

    bf16* XH = (bf16*)xh;  bf16* XL = (bf16*)xl;
    bf16* AH = (bf16*)ath; bf16* AL = (bf16*)atl;
    bf16* WH[6]; bf16* WL[6];
    for (int i = 0; i < 6; i++) { WH[i] = (bf16*)(wh + i * 65536); WL[i] = (bf16*)(wl + i * 65536); }

    // ---- input splits ----
    ksplit<<<DN * 64 / 256, 256>>>(xS, XH, XL, DN * 64);
    for (int i = 0; i < 6; i++)
        ksplit<<<64, 256>>>(Wref[i], WH[i], WL[i], 16384);

    // ---- phase 1: subset attention ----
    mma_proj_tc<<<DM / 128, 512, SMEMTC>>>(XH, XL, sub, WH[0], WL[0], q1, DM);
    mma_proj_tc<<<DM / 128, 512, SMEMTC>>>(XH, XL, sub, WH[1], WL[1], k1, DM);
    mma_proj_tc<<<DM / 128, 512, SMEMTC>>>(XH, XL, sub, WH[2], WL[2], v1, DM);
    attn_scores<<<DG, 256>>>(q1, k1, E);
    attn_apply<<<DG * 2, 256>>>(E, v1, AH, AL);

    // ---- phase 2: projections ----
    mma_proj_tc<<<DM / 128, 512, SMEMTC>>>(AH, AL, nullptr, WH[4], WL[4], ko, DM);
    mma_proj_tc<<<DM / 128, 512, SMEMTC>>>(AH, AL, nullptr, WH[5], WL[5], vo, DM);
    int nTilesN = (DN + 127) / 128;
    mma_proj_tc<<<nTilesN, 512, SMEMTC>>>(XH, XL, nullptr, WH[3], WL[3], q2, DN);
    mma_proj_tc<<<nTilesN, 512, SMEMTC>>>(XH, XL, nullptr, WH[4], WL[4], ks, DN);
    mma_proj_tc<<<nTilesN, 512, SMEMTC>>>(XH, XL, nullptr, WH[5], WL[5], vs, DN);

    // ---- phase 2: segment softmax aggregation ----
    rowdot<<<DN / 8, 256>>>(q2, ks, nullptr, ss, DN);
    rowdot<<<DM / 8, 256>>>(q2, ko, sub, so, DM);
    kinit_max<<<(DN + 255) / 256, 256>>>(ss, mx, DN);
    kseg_max<<<DM / 256, 256>>>(so, sub, mx);
    kout_init<<<DN * 64 / 256, 256>>>(ss, mx, vs, out);
    kocc_acc<<<DM * 64 / 256, 256>>>(so, sub, mx, vo, out);
    knorm<<<DN / 8, 256>>>(out);
}

// round 12
// speedup vs baseline: 1.9656x; 1.1395x over previous
#include <cuda_runtime.h>
#include <cuda_bf16.h>
#include <cstdint>

#define DN 200000
#define DDIM 256
#define DG 1024
#define DS 128
#define DM (DG*DS)

typedef __nv_bfloat16 bf16;

// ---------------- scratch: __device__ globals (no allocation allowed) --------
__device__ float          g_q1[(size_t)DM*DDIM];
__device__ float          g_k1[(size_t)DM*DDIM];
__device__ float          g_v1[(size_t)DM*DDIM];
__device__ float          g_E [(size_t)DG*DS*DS];
__device__ unsigned short g_ath[(size_t)DM*DDIM];   // att hi (bf16 bits)
__device__ unsigned short g_atl[(size_t)DM*DDIM];   // att lo
__device__ unsigned short g_xh [(size_t)DN*DDIM];   // xS hi
__device__ unsigned short g_xl [(size_t)DN*DDIM];   // xS lo
__device__ unsigned short g_wh [6*65536];           // weights hi
__device__ unsigned short g_wl [6*65536];           // weights lo
__device__ float          g_q2[(size_t)DN*DDIM];
__device__ float          g_vs[(size_t)DN*DDIM];
__device__ float          g_vo[(size_t)DM*DDIM];
__device__ float          g_ss[DN];
__device__ float          g_so[DM];
__device__ unsigned       g_mx[DN];

// ---------------- fp32 -> (hi,lo) bf16 split ---------------------------------
__device__ __forceinline__ void split_wr(bf16* H, bf16* L, float4 v) {
    bf16 h0 = __float2bfloat16(v.x), h1 = __float2bfloat16(v.y);
    bf16 h2 = __float2bfloat16(v.z), h3 = __float2bfloat16(v.w);
    bf16 l0 = __float2bfloat16(v.x - __bfloat162float(h0));
    bf16 l1 = __float2bfloat16(v.y - __bfloat162float(h1));
    bf16 l2 = __float2bfloat16(v.z - __bfloat162float(h2));
    bf16 l3 = __float2bfloat16(v.w - __bfloat162float(h3));
    ((__nv_bfloat162*)H)[0] = __halves2bfloat162(h0, h1);
    ((__nv_bfloat162*)H)[1] = __halves2bfloat162(h2, h3);
    ((__nv_bfloat162*)L)[0] = __halves2bfloat162(l0, l1);
    ((__nv_bfloat162*)L)[1] = __halves2bfloat162(l2, l3);
}

__global__ void ksplit(const float* __restrict__ x, bf16* __restrict__ hi,
                       bf16* __restrict__ lo, int n4) {
    int i = blockIdx.x * 256 + threadIdx.x;
    if (i < n4)
        split_wr(hi + 4 * (size_t)i, lo + 4 * (size_t)i, ((const float4*)x)[i]);
}

// ---------------- mma.sync bf16 GEMM + proj, cp.async pipelined --------------
// C[128,256] = proj(X@W^T); 3-term split Ahi*Bhi + Ahi*Blo + Alo*Bhi.
// Block 512 thr (16 warps), warp tile 64x32 (wm=wid&1, wn=wid>>1), K chunks 32.
// Optional fused dot: dotout[row] = C_row . dotq[dotg?dotg[row]:row] (skips C).
__device__ __forceinline__ void mma16816(float* d, const unsigned* a,
                                         unsigned b0, unsigned b1) {
    asm volatile(
        "mma.sync.aligned.m16n8k16.row.col.f32.bf16.bf16.f32 "
        "{%0,%1,%2,%3}, {%4,%5,%6,%7}, {%8,%9}, {%0,%1,%2,%3};"
        : "+f"(d[0]), "+f"(d[1]), "+f"(d[2]), "+f"(d[3])
        : "r"(a[0]), "r"(a[1]), "r"(a[2]), "r"(a[3]), "r"(b0), "r"(b1));
}
__device__ __forceinline__ void cpa16(uint32_t dst, const void* src) {
    asm volatile("cp.async.cg.shared.global [%0], [%1], 16;"
                 :: "r"(dst), "l"(src));
}
#define CP_COMMIT() asm volatile("cp.async.commit_group;")
#define CP_WAIT1()  asm volatile("cp.async.wait_group 1;")
#define CP_WAIT0()  asm volatile("cp.async.wait_group 0;")

#define ASTR 40                 // bf16 stride: 80B rows, frag banks all distinct
#define STG_BYTES 61440         // AH 10240 | AL 10240 | BH 20480 | BL 20480
#define OFF_AL 10240
#define OFF_BH 20480
#define OFF_BL 40960
#define OFF_RN (2*STG_BYTES)
#define OFF_RD (OFF_RN + 512)
#define OFF_RS (OFF_RD + 512)
#define SMEMTC (OFF_RS + 512)

__global__ void __launch_bounds__(512) mma_proj_tc(
    const bf16* __restrict__ Ahi, const bf16* __restrict__ Alo,
    const int* __restrict__ gidx,
    const bf16* __restrict__ Bhi, const bf16* __restrict__ Blo,
    float* __restrict__ C, int nrows,
    const float* __restrict__ dotq, const int* __restrict__ dotg,
    float* __restrict__ dotout)
{
    extern __shared__ __align__(16) char smc[];
    float* rn   = (float*)(smc + OFF_RN);
    float* rd   = (float*)(smc + OFF_RD);
    int*   rsrc = (int*)  (smc + OFF_RS);
    uint32_t sbase = (uint32_t)__cvta_generic_to_shared(smc);

    int tid = threadIdx.x;
    int wid = tid >> 5, lane = tid & 31;
    int wm = wid & 1, wn = wid >> 1;
    int g  = lane >> 2, tg = lane & 3;
    int r0 = blockIdx.x * 128;

    if (tid < 128) {
        int sr = r0 + tid;
        if (sr >= nrows) sr = nrows - 1;
        rsrc[tid] = gidx ? gidx[sr] : sr;
        rn[tid] = 0.f;
        rd[tid] = 0.f;
    }
    __syncthreads();

    int frow = tid >> 2;          // 0..127
    int fcg  = tid & 3;           // 16B group
    size_t asrc = (size_t)rsrc[frow] * 256;
    uint32_t dA = sbase + frow * 80 + fcg * 16;
    uint32_t dB1 = sbase + OFF_BH + frow * 80 + fcg * 16;
    uint32_t dB2 = sbase + OFF_BH + (frow + 128) * 80 + fcg * 16;
    const bf16* sB1h = Bhi + (size_t)frow * 256 + fcg * 8;
    const bf16* sB2h = Bhi + (size_t)(frow + 128) * 256 + fcg * 8;
    const bf16* sB1l = Blo + (size_t)frow * 256 + fcg * 8;
    const bf16* sB2l = Blo + (size_t)(frow + 128) * 256 + fcg * 8;
    const bf16* sAh = Ahi + asrc + fcg * 8;
    const bf16* sAl = Alo + asrc + fcg * 8;

    float acc[4][4][4];
#pragma unroll
    for (int mt = 0; mt < 4; mt++)
#pragma unroll
        for (int nt = 0; nt < 4; nt++)
#pragma unroll
            for (int j = 0; j < 4; j++) acc[mt][nt][j] = 0.f;

    // prefetch chunk 0 into stage 0
    {
        cpa16(dA, sAh); cpa16(dA + OFF_AL, sAl);
        cpa16(dB1, sB1h); cpa16(dB2, sB2h);
        cpa16(dB1 + 20480, sB1l); cpa16(dB2 + 20480, sB2l);
        CP_COMMIT();
    }

    for (int c = 0; c < 8; c++) {
        if (c < 7) {
            int k1 = (c + 1) * 32;
            uint32_t so = ((c + 1) & 1) * STG_BYTES;
            cpa16(dA + so, sAh + k1); cpa16(dA + OFF_AL + so, sAl + k1);
            cpa16(dB1 + so, sB1h + k1); cpa16(dB2 + so, sB2h + k1);
            cpa16(dB1 + 20480 + so, sB1l + k1); cpa16(dB2 + 20480 + so, sB2l + k1);
            CP_COMMIT();
            CP_WAIT1();
        } else {
            CP_WAIT0();
        }
        __syncthreads();

        char* stg = smc + (c & 1) * STG_BYTES;
        bf16* AsH = (bf16*)(stg);
        bf16* AsL = (bf16*)(stg + OFF_AL);
        bf16* BsH = (bf16*)(stg + OFF_BH);
        bf16* BsL = (bf16*)(stg + OFF_BL);

#pragma unroll
        for (int ks = 0; ks < 2; ks++) {
            int ko_ = ks * 16;
            unsigned af[4][4];
#pragma unroll
            for (int mt = 0; mt < 4; mt++) {
                const bf16* p = AsH + (wm * 64 + mt * 16 + g) * ASTR + ko_ + tg * 2;
                af[mt][0] = *(const unsigned*)(p);
                af[mt][1] = *(const unsigned*)(p + 8 * ASTR);
                af[mt][2] = *(const unsigned*)(p + 8);
                af[mt][3] = *(const unsigned*)(p + 8 * ASTR + 8);
            }
#pragma unroll
            for (int nt = 0; nt < 4; nt++) {
                const bf16* pb = BsH + (wn * 32 + nt * 8 + g) * ASTR + ko_ + tg * 2;
                const bf16* pl = BsL + (wn * 32 + nt * 8 + g) * ASTR + ko_ + tg * 2;
                unsigned bh0 = *(const unsigned*)(pb);
                unsigned bh1 = *(const unsigned*)(pb + 8);
                unsigned bl0 = *(const unsigned*)(pl);
                unsigned bl1 = *(const unsigned*)(pl + 8);
#pragma unroll
                for (int mt = 0; mt < 4; mt++)
                    mma16816(acc[mt][nt], af[mt], bh0, bh1);
#pragma unroll
                for (int mt = 0; mt < 4; mt++)
                    mma16816(acc[mt][nt], af[mt], bl0, bl1);
            }
            // third term: Alo * Bhi (reuse af registers)
#pragma unroll
            for (int mt = 0; mt < 4; mt++) {
                const bf16* p = AsL + (wm * 64 + mt * 16 + g) * ASTR + ko_ + tg * 2;
                af[mt][0] = *(const unsigned*)(p);
                af[mt][1] = *(const unsigned*)(p + 8 * ASTR);
                af[mt][2] = *(const unsigned*)(p + 8);
                af[mt][3] = *(const unsigned*)(p + 8 * ASTR + 8);
            }
#pragma unroll
            for (int nt = 0; nt < 4; nt++) {
                const bf16* pb = BsH + (wn * 32 + nt * 8 + g) * ASTR + ko_ + tg * 2;
                unsigned bh0 = *(const unsigned*)(pb);
                unsigned bh1 = *(const unsigned*)(pb + 8);
#pragma unroll
                for (int mt = 0; mt < 4; mt++)
                    mma16816(acc[mt][nt], af[mt], bh0, bh1);
            }
        }
        __syncthreads();
    }

    // ---- projection: per-row sumsq across 256 cols via smem atomics ----
#pragma unroll
    for (int mt = 0; mt < 4; mt++) {
        float s0 = 0.f, s1 = 0.f;
#pragma unroll
        for (int nt = 0; nt < 4; nt++) {
            s0 += acc[mt][nt][0] * acc[mt][nt][0] + acc[mt][nt][1] * acc[mt][nt][1];
            s1 += acc[mt][nt][2] * acc[mt][nt][2] + acc[mt][nt][3] * acc[mt][nt][3];
        }
        s0 += __shfl_xor_sync(0xffffffffu, s0, 1);
        s0 += __shfl_xor_sync(0xffffffffu, s0, 2);
        s1 += __shfl_xor_sync(0xffffffffu, s1, 1);
        s1 += __shfl_xor_sync(0xffffffffu, s1, 2);
        if (tg == 0) {
            atomicAdd(&rn[wm * 64 + mt * 16 + g], s0);
            atomicAdd(&rn[wm * 64 + mt * 16 + 8 + g], s1);
        }
    }
    __syncthreads();

#pragma unroll
    for (int mt = 0; mt < 4; mt++) {
        int rl = wm * 64 + mt * 16 + g;
        float sa = rsqrtf(rn[rl]);
        float sb = rsqrtf(rn[rl + 8]);
        bool oka = (r0 + rl) < nrows;
        bool okb = (r0 + rl + 8) < nrows;
#pragma unroll
        for (int nt = 0; nt < 4; nt++) {
            acc[mt][nt][0] *= sa; acc[mt][nt][1] *= sa;
            acc[mt][nt][2] *= sb; acc[mt][nt][3] *= sb;
        }
        if (C) {
            float* ca = C + (size_t)(r0 + rl) * 256;
            float* cb = C + (size_t)(r0 + rl + 8) * 256;
#pragma unroll
            for (int nt = 0; nt < 4; nt++) {
                int col = wn * 32 + nt * 8 + tg * 2;
                if (oka) *(float2*)(ca + col) =
                    make_float2(acc[mt][nt][0], acc[mt][nt][1]);
                if (okb) *(float2*)(cb + col) =
                    make_float2(acc[mt][nt][2], acc[mt][nt][3]);
            }
        }
        if (dotq) {
            float da = 0.f, db = 0.f;
            if (oka) {
                int qa = dotg ? dotg[r0 + rl] : (r0 + rl);
                const float* qp = dotq + (size_t)qa * 256;
#pragma unroll
                for (int nt = 0; nt < 4; nt++) {
                    float2 q = *(const float2*)(qp + wn * 32 + nt * 8 + tg * 2);
                    da += acc[mt][nt][0] * q.x + acc[mt][nt][1] * q.y;
                }
            }
            if (okb) {
                int qb = dotg ? dotg[r0 + rl + 8] : (r0 + rl + 8);
                const float* qp = dotq + (size_t)qb * 256;
#pragma unroll
                for (int nt = 0; nt < 4; nt++) {
                    float2 q = *(const float2*)(qp + wn * 32 + nt * 8 + tg * 2);
                    db += acc[mt][nt][2] * q.x + acc[mt][nt][3] * q.y;
                }
            }
            da += __shfl_xor_sync(0xffffffffu, da, 1);
            da += __shfl_xor_sync(0xffffffffu, da, 2);
            db += __shfl_xor_sync(0xffffffffu, db, 1);
            db += __shfl_xor_sync(0xffffffffu, db, 2);
            if (tg == 0) {
                atomicAdd(&rd[rl], da);
                atomicAdd(&rd[rl + 8], db);
            }
        }
    }
    if (dotq) {
        __syncthreads();
        if (tid < 128 && (r0 + tid) < nrows) dotout[r0 + tid] = rd[tid];
    }
}

// ---------------- packed f32x2 helpers (FFMA2 path, attention) ---------------
__device__ __forceinline__ unsigned long long pack2(float x, float y) {
    unsigned long long r;
    asm("mov.b64 %0, {%1,%2};" : "=l"(r)
        : "r"(__float_as_uint(x)), "r"(__float_as_uint(y)));
    return r;
}
__device__ __forceinline__ void fma2(unsigned long long& d,
                                     unsigned long long a, unsigned long long b) {
    asm("fma.rn.f32x2 %0, %1, %2, %0;" : "+l"(d) : "l"(a), "l"(b));
}
__device__ __forceinline__ float2 unpack2(unsigned long long r) {
    unsigned lo, hi;
    asm("mov.b64 {%0,%1}, %2;" : "=r"(lo), "=r"(hi) : "l"(r));
    return make_float2(__uint_as_float(lo), __uint_as_float(hi));
}
__device__ __forceinline__ unsigned encf(float f) {
    unsigned u = __float_as_uint(f);
    return (u & 0x80000000u) ? ~u : (u | 0x80000000u);
}
__device__ __forceinline__ float decf(unsigned u) {
    return __uint_as_float((u & 0x80000000u) ? (u & 0x7fffffffu) : ~u);
}

// -------- per-group scores: E = exp(Q@K^T - rowmax) --------------------------
#define QSTR 132
#define KSTR 130

__global__ __launch_bounds__(256) void attn_scores(
    const float* __restrict__ Q, const float* __restrict__ K, float* __restrict__ E)
{
    __shared__ float Qs[32 * QSTR];
    __shared__ float Ks[32 * KSTR];
    __shared__ float pm[128 * 17];

    int tid = threadIdx.x;
    int lane = tid & 31;
    int w = tid >> 5;
    int rg = w * 2 + (lane >> 4);
    int lc = lane & 15;
    int g = blockIdx.x;
    const float* Qg = Q + (size_t)g * 128 * 256;
    const float* Kg = K + (size_t)g * 128 * 256;

    unsigned long long acc[8][4];
#pragma unroll
    for (int i = 0; i < 8; i++) { acc[i][0]=0ULL; acc[i][1]=0ULL; acc[i][2]=0ULL; acc[i][3]=0ULL; }

    for (int k0 = 0; k0 < 256; k0 += 32) {
#pragma unroll
        for (int e = 0; e < 4; e++) {
            int idx = tid + e * 256;
            int row = idx >> 3, qq = idx & 7;
            float4 v = *(const float4*)(Qg + (size_t)row * 256 + (k0 + qq * 4));
            Qs[(qq*4+0)*QSTR + row] = v.x; Qs[(qq*4+1)*QSTR + row] = v.y;
            Qs[(qq*4+2)*QSTR + row] = v.z; Qs[(qq*4+3)*QSTR + row] = v.w;
            float4 u = *(const float4*)(Kg + (size_t)row * 256 + (k0 + qq * 4));
            Ks[(qq*4+0)*KSTR + row] = u.x; Ks[(qq*4+1)*KSTR + row] = u.y;
            Ks[(qq*4+2)*KSTR + row] = u.z; Ks[(qq*4+3)*KSTR + row] = u.w;
        }
        __syncthreads();
#pragma unroll
        for (int kk = 0; kk < 32; kk++) {
            float4 xa = *(const float4*)(Qs + kk * QSTR + rg * 8);
            float4 xb = *(const float4*)(Qs + kk * QSTR + rg * 8 + 4);
            const unsigned long long* wp = (const unsigned long long*)(Ks + kk * KSTR);
            unsigned long long b0 = wp[lc*2],      b1 = wp[lc*2 + 1];
            unsigned long long b2 = wp[32 + lc*2], b3 = wp[32 + lc*2 + 1];
            float xs8[8] = {xa.x, xa.y, xa.z, xa.w, xb.x, xb.y, xb.z, xb.w};
#pragma unroll
            for (int i = 0; i < 8; i++) {
                unsigned long long a = pack2(xs8[i], xs8[i]);
                fma2(acc[i][0], a, b0); fma2(acc[i][1], a, b1);
                fma2(acc[i][2], a, b2); fma2(acc[i][3], a, b3);
            }
        }
        __syncthreads();
    }

    float c[8][8];
    int rb = rg * 8;
#pragma unroll
    for (int i = 0; i < 8; i++) {
        float2 p0 = unpack2(acc[i][0]), p1 = unpack2(acc[i][1]);
        float2 p2 = unpack2(acc[i][2]), p3 = unpack2(acc[i][3]);
        c[i][0]=p0.x; c[i][1]=p0.y; c[i][2]=p1.x; c[i][3]=p1.y;
        c[i][4]=p2.x; c[i][5]=p2.y; c[i][6]=p3.x; c[i][7]=p3.y;
        float m = c[i][0];
#pragma unroll
        for (int j = 1; j < 8; j++) m = fmaxf(m, c[i][j]);
        pm[(rb + i) * 17 + lc] = m;
    }
    __syncthreads();
#pragma unroll
    for (int i = 0; i < 8; i++) {
        float m = pm[(rb + i) * 17];
#pragma unroll
        for (int t = 1; t < 16; t++) m = fmaxf(m, pm[(rb + i) * 17 + t]);
        size_t base = (size_t)g * 16384 + (size_t)(rb + i) * 128;
        *(float4*)(E + base + lc * 4) = make_float4(
            __expf(c[i][0]-m), __expf(c[i][1]-m), __expf(c[i][2]-m), __expf(c[i][3]-m));
        *(float4*)(E + base + 64 + lc * 4) = make_float4(
            __expf(c[i][4]-m), __expf(c[i][5]-m), __expf(c[i][6]-m), __expf(c[i][7]-m));
    }
}

// -------- per-group apply: att_half = E @ V_half -> split bf16 out -----------
#define ESTR 132
#define VSTR 132

__global__ __launch_bounds__(256) void attn_apply(
    const float* __restrict__ E, const float* __restrict__ V,
    bf16* __restrict__ Oh, bf16* __restrict__ Ol)
{
    __shared__ float Es[32 * ESTR];
    __shared__ float Vs[32 * VSTR];

    int tid = threadIdx.x;
    int lane = tid & 31;
    int w = tid >> 5;
    int rg = w * 2 + (lane >> 4);
    int lc = lane & 15;
    int g = blockIdx.x >> 1, half = blockIdx.x & 1;
    const float* Eg = E + (size_t)g * 16384;
    const float* Vg = V + (size_t)g * 128 * 256 + half * 128;

    unsigned long long acc[8][4];
#pragma unroll
    for (int i = 0; i < 8; i++) { acc[i][0]=0ULL; acc[i][1]=0ULL; acc[i][2]=0ULL; acc[i][3]=0ULL; }

    for (int k0 = 0; k0 < 128; k0 += 32) {
#pragma unroll
        for (int e = 0; e < 4; e++) {
            int idx = tid + e * 256;
            int row = idx >> 3, qq = idx & 7;
            float4 v = *(const float4*)(Eg + (size_t)row * 128 + (k0 + qq * 4));
            Es[(qq*4+0)*ESTR + row] = v.x; Es[(qq*4+1)*ESTR + row] = v.y;
            Es[(qq*4+2)*ESTR + row] = v.z; Es[(qq*4+3)*ESTR + row] = v.w;
            int kk = idx >> 5, cv = idx & 31;
            float4 u = *(const float4*)(Vg + (size_t)(k0 + kk) * 256 + cv * 4);
            *(float4*)(Vs + kk * VSTR + cv * 4) = u;
        }
        __syncthreads();
#pragma unroll
        for (int kk = 0; kk < 32; kk++) {
            float4 xa = *(const float4*)(Es + kk * ESTR + rg * 8);
            float4 xb = *(const float4*)(Es + kk * ESTR + rg * 8 + 4);
            const unsigned long long* wp = (const unsigned long long*)(Vs + kk * VSTR);
            unsigned long long b0 = wp[lc*2],      b1 = wp[lc*2 + 1];
            unsigned long long b2 = wp[32 + lc*2], b3 = wp[32 + lc*2 + 1];
            float xs8[8] = {xa.x, xa.y, xa.z, xa.w, xb.x, xb.y, xb.z, xb.w};
#pragma unroll
            for (int i = 0; i < 8; i++) {
                unsigned long long a = pack2(xs8[i], xs8[i]);
                fma2(acc[i][0], a, b0); fma2(acc[i][1], a, b1);
                fma2(acc[i][2], a, b2); fma2(acc[i][3], a, b3);
            }
        }
        __syncthreads();
    }

    int rb = rg * 8;
#pragma unroll
    for (int i = 0; i < 8; i++) {
        float2 p0 = unpack2(acc[i][0]), p1 = unpack2(acc[i][1]);
        float2 p2 = unpack2(acc[i][2]), p3 = unpack2(acc[i][3]);
        size_t base = (size_t)(g * 128 + rb + i) * 256 + half * 128;
        split_wr(Oh + base + lc * 4,      Ol + base + lc * 4,
                 make_float4(p0.x, p0.y, p1.x, p1.y));
        split_wr(Oh + base + 64 + lc * 4, Ol + base + 64 + lc * 4,
                 make_float4(p2.x, p2.y, p3.x, p3.y));
    }
}

// ---------------- segment phase ---------------------------------------------
__global__ void kinit_max(const float* __restrict__ ss, unsigned* __restrict__ mx, int n)
{
    int i = blockIdx.x * 256 + threadIdx.x;
    if (i < n) mx[i] = encf(ss[i]);
}

__global__ void kseg_max(const float* __restrict__ so, const int* __restrict__ seg,
                         unsigned* __restrict__ mx)
{
    int i = blockIdx.x * 256 + threadIdx.x;
    atomicMax(&mx[seg[i]], encf(so[i]));
}

__global__ void kout_init(const float* __restrict__ ss, const unsigned* __restrict__ mx,
                          const float* __restrict__ vs, float* __restrict__ out)
{
    int t = blockIdx.x * 256 + threadIdx.x;
    int i = t >> 6, j = t & 63;
    float e = __expf(ss[i] - decf(mx[i]));
    float4 v = ((const float4*)vs)[(size_t)i * 64 + j];
    ((float4*)out)[(size_t)i * 64 + j] = make_float4(e*v.x, e*v.y, e*v.z, e*v.w);
}

__global__ void kocc_acc(const float* __restrict__ so, const int* __restrict__ seg,
                         const unsigned* __restrict__ mx, const float* __restrict__ vo,
                         float* __restrict__ out)
{
    int t = blockIdx.x * 256 + threadIdx.x;
    int i = t >> 6, j = t & 63;
    int n = seg[i];
    float e = __expf(so[i] - decf(mx[n]));
    float4 v = ((const float4*)vo)[(size_t)i * 64 + j];
    float* p = out + (size_t)n * 256 + j * 4;
    asm volatile("red.global.add.v4.f32 [%0], {%1, %2, %3, %4};"
                 :: "l"(p), "f"(e * v.x), "f"(e * v.y), "f"(e * v.z), "f"(e * v.w)
                 : "memory");
}

__global__ void knorm(float* __restrict__ out)
{
    int row = blockIdx.x * 8 + (threadIdx.x >> 5);
    int lane = threadIdx.x & 31;
    float4* p = (float4*)(out + (size_t)row * 256);
    float4 a = p[lane], b = p[lane + 32];
    float s = a.x*a.x + a.y*a.y + a.z*a.z + a.w*a.w
            + b.x*b.x + b.y*b.y + b.z*b.z + b.w*b.w;
#pragma unroll
    for (int o = 16; o; o >>= 1) s += __shfl_xor_sync(0xffffffffu, s, o);
    float r = rsqrtf(s);
    p[lane]      = make_float4(a.x*r, a.y*r, a.z*r, a.w*r);
    p[lane + 32] = make_float4(b.x*r, b.y*r, b.z*r, b.w*r);
}

// ---------------- launch -----------------------------------------------------
extern "C" void kernel_launch(void* const* d_in, const int* in_sizes, int n_in,
                              void* d_out, int out_size)
{
    const float* xS  = (const float*)d_in[0];
    const int*   sub = (const int*)  d_in[1];
    const float* Wref[6] = { (const float*)d_in[2], (const float*)d_in[3],
                             (const float*)d_in[4], (const float*)d_in[5],
                             (const float*)d_in[6], (const float*)d_in[7] };
    float* out = (float*)d_out;

    float *q1, *k1, *v1, *E, *q2, *vs, *vo, *ss, *so;
    unsigned short *ath, *atl, *xh, *xl, *wh, *wl;
    unsigned* mx;
    cudaGetSymbolAddress((void**)&q1,  g_q1);
    cudaGetSymbolAddress((void**)&k1,  g_k1);
    cudaGetSymbolAddress((void**)&v1,  g_v1);
    cudaGetSymbolAddress((void**)&E,   g_E);
    cudaGetSymbolAddress((void**)&ath, g_ath);
    cudaGetSymbolAddress((void**)&atl, g_atl);
    cudaGetSymbolAddress((void**)&xh,  g_xh);
    cudaGetSymbolAddress((void**)&xl,  g_xl);
    cudaGetSymbolAddress((void**)&wh,  g_wh);
    cudaGetSymbolAddress((void**)&wl,  g_wl);
    cudaGetSymbolAddress((void**)&q2,  g_q2);
    cudaGetSymbolAddress((void**)&vs,  g_vs);
    cudaGetSymbolAddress((void**)&vo,  g_vo);
    cudaGetSymbolAddress((void**)&ss,  g_ss);
    cudaGetSymbolAddress((void**)&so,  g_so);
    cudaGetSymbolAddress((void**)&mx,  g_mx);

    cudaFuncSetAttribute(mma_proj_tc, cudaFuncAttributeMaxDynamicSharedMemorySize, SMEMTC);

    bf16* XH = (bf16*)xh;  bf16* XL = (bf16*)xl;
    bf16* AH = (bf16*)ath; bf16* AL = (bf16*)atl;
    bf16* WH[6]; bf16* WL[6];
    for (int i = 0; i < 6; i++) { WH[i] = (bf16*)(wh + i * 65536); WL[i] = (bf16*)(wl + i * 65536); }

    // ---- input splits ----
    ksplit<<<DN * 64 / 256, 256>>>(xS, XH, XL, DN * 64);
    for (int i = 0; i < 6; i++)
        ksplit<<<64, 256>>>(Wref[i], WH[i], WL[i], 16384);

    // ---- phase 1: subset attention ----
    mma_proj_tc<<<DM / 128, 512, SMEMTC>>>(XH, XL, sub, WH[0], WL[0], q1, DM,
                                           nullptr, nullptr, nullptr);
    mma_proj_tc<<<DM / 128, 512, SMEMTC>>>(XH, XL, sub, WH[1], WL[1], k1, DM,
                                           nullptr, nullptr, nullptr);
    mma_proj_tc<<<DM / 128, 512, SMEMTC>>>(XH, XL, sub, WH[2], WL[2], v1, DM,
                                           nullptr, nullptr, nullptr);
    attn_scores<<<DG, 256>>>(q1, k1, E);
    attn_apply<<<DG * 2, 256>>>(E, v1, AH, AL);

    // ---- phase 2: projections (q2 first; ks/ko fused into dot epilogues) ----
    int nTilesN = (DN + 127) / 128;
    mma_proj_tc<<<nTilesN, 512, SMEMTC>>>(XH, XL, nullptr, WH[3], WL[3], q2, DN,
                                          nullptr, nullptr, nullptr);
    mma_proj_tc<<<nTilesN, 512, SMEMTC>>>(XH, XL, nullptr, WH[4], WL[4],
                                          nullptr, DN, q2, nullptr, ss);
    mma_proj_tc<<<DM / 128, 512, SMEMTC>>>(AH, AL, nullptr, WH[4], WL[4],
                                           nullptr, DM, q2, sub, so);
    mma_proj_tc<<<nTilesN, 512, SMEMTC>>>(XH, XL, nullptr, WH[5], WL[5], vs, DN,
                                          nullptr, nullptr, nullptr);
    mma_proj_tc<<<DM / 128, 512, SMEMTC>>>(AH, AL, nullptr, WH[5], WL[5], vo, DM,
                                           nullptr, nullptr, nullptr);

    // ---- phase 2: segment softmax aggregation ----
    kinit_max<<<(DN + 255) / 256, 256>>>(ss, mx, DN);
    kseg_max<<<DM / 256, 256>>>(so, sub, mx);
    kout_init<<<DN * 64 / 256, 256>>>(ss, mx, vs, out);
    kocc_acc<<<DM * 64 / 256, 256>>>(so, sub, mx, vo, out);
    knorm<<<DN / 8, 256>>>(out);
}

// round 13
// speedup vs baseline: 1.9734x; 1.0040x over previous
#include <cuda_runtime.h>
#include <cuda_bf16.h>
#include <cstdint>

#define DN 200000
#define DDIM 256
#define DG 1024
#define DS 128
#define DM (DG*DS)

typedef __nv_bfloat16 bf16;

// ---------------- scratch: __device__ globals (no allocation allowed) --------
__device__ float          g_q1[(size_t)DM*DDIM];
__device__ float          g_k1[(size_t)DM*DDIM];
__device__ float          g_v1[(size_t)DM*DDIM];
__device__ float          g_E [(size_t)DG*DS*DS];
__device__ unsigned short g_ath[(size_t)DM*DDIM];   // att hi (bf16 bits)
__device__ unsigned short g_atl[(size_t)DM*DDIM];   // att lo
__device__ unsigned short g_xh [(size_t)DN*DDIM];   // xS hi
__device__ unsigned short g_xl [(size_t)DN*DDIM];   // xS lo
__device__ unsigned short g_wh [6*65536];           // weights hi
__device__ unsigned short g_wl [6*65536];           // weights lo
__device__ float          g_q2[(size_t)DN*DDIM];
__device__ float          g_vs[(size_t)DN*DDIM];
__device__ float          g_vo[(size_t)DM*DDIM];
__device__ float          g_ss[DN];
__device__ float          g_so[DM];
__device__ unsigned       g_mx[DN];

// ---------------- fp32 -> (hi,lo) bf16 split ---------------------------------
__device__ __forceinline__ void split_wr(bf16* H, bf16* L, float4 v) {
    bf16 h0 = __float2bfloat16(v.x), h1 = __float2bfloat16(v.y);
    bf16 h2 = __float2bfloat16(v.z), h3 = __float2bfloat16(v.w);
    bf16 l0 = __float2bfloat16(v.x - __bfloat162float(h0));
    bf16 l1 = __float2bfloat16(v.y - __bfloat162float(h1));
    bf16 l2 = __float2bfloat16(v.z - __bfloat162float(h2));
    bf16 l3 = __float2bfloat16(v.w - __bfloat162float(h3));
    ((__nv_bfloat162*)H)[0] = __halves2bfloat162(h0, h1);
    ((__nv_bfloat162*)H)[1] = __halves2bfloat162(h2, h3);
    ((__nv_bfloat162*)L)[0] = __halves2bfloat162(l0, l1);
    ((__nv_bfloat162*)L)[1] = __halves2bfloat162(l2, l3);
}

__global__ void ksplit(const float* __restrict__ x, bf16* __restrict__ hi,
                       bf16* __restrict__ lo, int n4) {
    int i = blockIdx.x * 256 + threadIdx.x;
    if (i < n4)
        split_wr(hi + 4 * (size_t)i, lo + 4 * (size_t)i, ((const float4*)x)[i]);
}

// all six 256x256 weights in one launch: 6*16384 float4 elements
__global__ void ksplit6(const float* w0, const float* w1, const float* w2,
                        const float* w3, const float* w4, const float* w5,
                        bf16* __restrict__ hi, bf16* __restrict__ lo) {
    int i = blockIdx.x * 256 + threadIdx.x;   // 0 .. 98303
    int which = i >> 14, off = i & 16383;
    const float* w = (which == 0) ? w0 : (which == 1) ? w1 : (which == 2) ? w2
                   : (which == 3) ? w3 : (which == 4) ? w4 : w5;
    split_wr(hi + 4 * (size_t)i, lo + 4 * (size_t)i, ((const float4*)w)[off]);
}

// ---------------- mma.sync bf16 GEMM + proj, cp.async pipelined --------------
// C[128,256] = proj(X@W^T); 3-term split Ahi*Bhi + Ahi*Blo + Alo*Bhi.
// Block 256 thr (8 warps), warp tile 64x64 (wm=wid&1, wn=wid>>1), K chunks 32.
// Optional fused dot: dotout[row] = C_row . dotq[dotg?dotg[row]:row].
__device__ __forceinline__ void mma16816(float* d, const unsigned* a,
                                         unsigned b0, unsigned b1) {
    asm volatile(
        "mma.sync.aligned.m16n8k16.row.col.f32.bf16.bf16.f32 "
        "{%0,%1,%2,%3}, {%4,%5,%6,%7}, {%8,%9}, {%0,%1,%2,%3};"
        : "+f"(d[0]), "+f"(d[1]), "+f"(d[2]), "+f"(d[3])
        : "r"(a[0]), "r"(a[1]), "r"(a[2]), "r"(a[3]), "r"(b0), "r"(b1));
}
__device__ __forceinline__ void cpa16(uint32_t dst, const void* src) {
    asm volatile("cp.async.cg.shared.global [%0], [%1], 16;"
                 :: "r"(dst), "l"(src));
}
#define CP_COMMIT() asm volatile("cp.async.commit_group;")
#define CP_WAIT1()  asm volatile("cp.async.wait_group 1;")
#define CP_WAIT0()  asm volatile("cp.async.wait_group 0;")

#define ASTR 40                 // bf16 stride: 80B rows, frag banks all distinct
#define STG_BYTES 61440         // AH 10240 | AL 10240 | BH 20480 | BL 20480
#define OFF_AL 10240
#define OFF_BH 20480
#define OFF_RN (2*STG_BYTES)
#define OFF_RD (OFF_RN + 512)
#define OFF_RS (OFF_RD + 512)
#define SMEMTC (OFF_RS + 512)

__global__ void __launch_bounds__(256) mma_proj_tc(
    const bf16* __restrict__ Ahi, const bf16* __restrict__ Alo,
    const int* __restrict__ gidx,
    const bf16* __restrict__ Bhi, const bf16* __restrict__ Blo,
    float* __restrict__ C, int nrows,
    const float* __restrict__ dotq, const int* __restrict__ dotg,
    float* __restrict__ dotout)
{
    extern __shared__ __align__(16) char smc[];
    float* rn   = (float*)(smc + OFF_RN);
    float* rd   = (float*)(smc + OFF_RD);
    int*   rsrc = (int*)  (smc + OFF_RS);
    uint32_t sbase = (uint32_t)__cvta_generic_to_shared(smc);

    int tid = threadIdx.x;
    int wid = tid >> 5, lane = tid & 31;
    int wm = wid & 1, wn = wid >> 1;           // wm: 2x64 rows, wn: 4x64 cols
    int g  = lane >> 2, tg = lane & 3;
    int r0 = blockIdx.x * 128;

    if (tid < 128) {
        int sr = r0 + tid;
        if (sr >= nrows) sr = nrows - 1;
        rsrc[tid] = gidx ? gidx[sr] : sr;
        rn[tid] = 0.f;
        rd[tid] = 0.f;
    }
    __syncthreads();

    // fill roles: each thread owns one 16B segment column (seg = tid&3)
    int arow0 = tid >> 2, seg = tid & 3;       // arow0: 0..63
    size_t ab0 = (size_t)rsrc[arow0]      * 256 + seg * 8;
    size_t ab1 = (size_t)rsrc[arow0 + 64] * 256 + seg * 8;
    uint32_t dA0 = sbase + arow0 * 80 + seg * 16;
    uint32_t dA1 = sbase + (arow0 + 64) * 80 + seg * 16;

    float acc[4][8][4];
#pragma unroll
    for (int mt = 0; mt < 4; mt++)
#pragma unroll
        for (int nt = 0; nt < 8; nt++)
#pragma unroll
            for (int j = 0; j < 4; j++) acc[mt][nt][j] = 0.f;

    // prefetch chunk 0 into stage 0
#pragma unroll
    for (int pc = 0; pc < 1; pc++) {
        cpa16(dA0, Ahi + ab0); cpa16(dA0 + OFF_AL, Alo + ab0);
        cpa16(dA1, Ahi + ab1); cpa16(dA1 + OFF_AL, Alo + ab1);
#pragma unroll
        for (int e = 0; e < 4; e++) {
            int row = arow0 + e * 64;
            uint32_t dB = sbase + OFF_BH + row * 80 + seg * 16;
            const bf16* bsrc = Bhi + (size_t)row * 256 + seg * 8;
            const bf16* lsrc = Blo + (size_t)row * 256 + seg * 8;
            cpa16(dB, bsrc); cpa16(dB + 20480, lsrc);
        }
        CP_COMMIT();
    }

    for (int c = 0; c < 8; c++) {
        if (c < 7) {
            int k1 = (c + 1) * 32;
            uint32_t so = ((c + 1) & 1) * STG_BYTES;
            cpa16(dA0 + so, Ahi + ab0 + k1); cpa16(dA0 + OFF_AL + so, Alo + ab0 + k1);
            cpa16(dA1 + so, Ahi + ab1 + k1); cpa16(dA1 + OFF_AL + so, Alo + ab1 + k1);
#pragma unroll
            for (int e = 0; e < 4; e++) {
                int row = arow0 + e * 64;
                uint32_t dB = sbase + OFF_BH + row * 80 + seg * 16 + so;
                cpa16(dB, Bhi + (size_t)row * 256 + seg * 8 + k1);
                cpa16(dB + 20480, Blo + (size_t)row * 256 + seg * 8 + k1);
            }
            CP_COMMIT();
            CP_WAIT1();
        } else {
            CP_WAIT0();
        }
        __syncthreads();

        char* stg = smc + (c & 1) * STG_BYTES;
        bf16* AsH = (bf16*)(stg);
        bf16* AsL = (bf16*)(stg + OFF_AL);
        bf16* BsH = (bf16*)(stg + OFF_BH);
        bf16* BsL = (bf16*)(stg + OFF_BH + 20480);

#pragma unroll
        for (int ks = 0; ks < 2; ks++) {
            int ko_ = ks * 16;
            unsigned af[4][4];
#pragma unroll
            for (int mt = 0; mt < 4; mt++) {
                const bf16* p = AsH + (wm * 64 + mt * 16 + g) * ASTR + ko_ + tg * 2;
                af[mt][0] = *(const unsigned*)(p);
                af[mt][1] = *(const unsigned*)(p + 8 * ASTR);
                af[mt][2] = *(const unsigned*)(p + 8);
                af[mt][3] = *(const unsigned*)(p + 8 * ASTR + 8);
            }
            unsigned bh[8][2], bl[8][2];
#pragma unroll
            for (int nt = 0; nt < 8; nt++) {
                const bf16* pb = BsH + (wn * 64 + nt * 8 + g) * ASTR + ko_ + tg * 2;
                const bf16* pl = BsL + (wn * 64 + nt * 8 + g) * ASTR + ko_ + tg * 2;
                bh[nt][0] = *(const unsigned*)(pb);
                bh[nt][1] = *(const unsigned*)(pb + 8);
                bl[nt][0] = *(const unsigned*)(pl);
                bl[nt][1] = *(const unsigned*)(pl + 8);
            }
            // term1: Ahi * Bhi
#pragma unroll
            for (int nt = 0; nt < 8; nt++)
#pragma unroll
                for (int mt = 0; mt < 4; mt++)
                    mma16816(acc[mt][nt], af[mt], bh[nt][0], bh[nt][1]);
            // term2: Ahi * Blo
#pragma unroll
            for (int nt = 0; nt < 8; nt++)
#pragma unroll
                for (int mt = 0; mt < 4; mt++)
                    mma16816(acc[mt][nt], af[mt], bl[nt][0], bl[nt][1]);
            // term3: Alo * Bhi (reload A frags)
#pragma unroll
            for (int mt = 0; mt < 4; mt++) {
                const bf16* p = AsL + (wm * 64 + mt * 16 + g) * ASTR + ko_ + tg * 2;
                af[mt][0] = *(const unsigned*)(p);
                af[mt][1] = *(const unsigned*)(p + 8 * ASTR);
                af[mt][2] = *(const unsigned*)(p + 8);
                af[mt][3] = *(const unsigned*)(p + 8 * ASTR + 8);
            }
#pragma unroll
            for (int nt = 0; nt < 8; nt++)
#pragma unroll
                for (int mt = 0; mt < 4; mt++)
                    mma16816(acc[mt][nt], af[mt], bh[nt][0], bh[nt][1]);
        }
        __syncthreads();
    }

    // ---- projection: per-row sumsq across 256 cols via smem atomics ----
#pragma unroll
    for (int mt = 0; mt < 4; mt++) {
        float s0 = 0.f, s1 = 0.f;
#pragma unroll
        for (int nt = 0; nt < 8; nt++) {
            s0 += acc[mt][nt][0] * acc[mt][nt][0] + acc[mt][nt][1] * acc[mt][nt][1];
            s1 += acc[mt][nt][2] * acc[mt][nt][2] + acc[mt][nt][3] * acc[mt][nt][3];
        }
        s0 += __shfl_xor_sync(0xffffffffu, s0, 1);
        s0 += __shfl_xor_sync(0xffffffffu, s0, 2);
        s1 += __shfl_xor_sync(0xffffffffu, s1, 1);
        s1 += __shfl_xor_sync(0xffffffffu, s1, 2);
        if (tg == 0) {
            atomicAdd(&rn[wm * 64 + mt * 16 + g], s0);
            atomicAdd(&rn[wm * 64 + mt * 16 + 8 + g], s1);
        }
    }
    __syncthreads();

#pragma unroll
    for (int mt = 0; mt < 4; mt++) {
        int rl = wm * 64 + mt * 16 + g;
        float sa = rsqrtf(rn[rl]);
        float sb = rsqrtf(rn[rl + 8]);
        bool oka = (r0 + rl) < nrows;
        bool okb = (r0 + rl + 8) < nrows;
#pragma unroll
        for (int nt = 0; nt < 8; nt++) {
            acc[mt][nt][0] *= sa; acc[mt][nt][1] *= sa;
            acc[mt][nt][2] *= sb; acc[mt][nt][3] *= sb;
        }
        if (C) {
            float* ca = C + (size_t)(r0 + rl) * 256;
            float* cb = C + (size_t)(r0 + rl + 8) * 256;
#pragma unroll
            for (int nt = 0; nt < 8; nt++) {
                int col = wn * 64 + nt * 8 + tg * 2;
                if (oka) *(float2*)(ca + col) =
                    make_float2(acc[mt][nt][0], acc[mt][nt][1]);
                if (okb) *(float2*)(cb + col) =
                    make_float2(acc[mt][nt][2], acc[mt][nt][3]);
            }
        }
        if (dotq) {
            float da = 0.f, db = 0.f;
            if (oka) {
                int qa = dotg ? dotg[r0 + rl] : (r0 + rl);
                const float* qp = dotq + (size_t)qa * 256;
#pragma unroll
                for (int nt = 0; nt < 8; nt++) {
                    float2 q = *(const float2*)(qp + wn * 64 + nt * 8 + tg * 2);
                    da += acc[mt][nt][0] * q.x + acc[mt][nt][1] * q.y;
                }
            }
            if (okb) {
                int qb = dotg ? dotg[r0 + rl + 8] : (r0 + rl + 8);
                const float* qp = dotq + (size_t)qb * 256;
#pragma unroll
                for (int nt = 0; nt < 8; nt++) {
                    float2 q = *(const float2*)(qp + wn * 64 + nt * 8 + tg * 2);
                    db += acc[mt][nt][2] * q.x + acc[mt][nt][3] * q.y;
                }
            }
            da += __shfl_xor_sync(0xffffffffu, da, 1);
            da += __shfl_xor_sync(0xffffffffu, da, 2);
            db += __shfl_xor_sync(0xffffffffu, db, 1);
            db += __shfl_xor_sync(0xffffffffu, db, 2);
            if (tg == 0) {
                atomicAdd(&rd[rl], da);
                atomicAdd(&rd[rl + 8], db);
            }
        }
    }
    if (dotq) {
        __syncthreads();
        if (tid < 128 && (r0 + tid) < nrows) dotout[r0 + tid] = rd[tid];
    }
}

// ---------------- packed f32x2 helpers (FFMA2 path, attention) ---------------
__device__ __forceinline__ unsigned long long pack2(float x, float y) {
    unsigned long long r;
    asm("mov.b64 %0, {%1,%2};" : "=l"(r)
        : "r"(__float_as_uint(x)), "r"(__float_as_uint(y)));
    return r;
}
__device__ __forceinline__ void fma2(unsigned long long& d,
                                     unsigned long long a, unsigned long long b) {
    asm("fma.rn.f32x2 %0, %1, %2, %0;" : "+l"(d) : "l"(a), "l"(b));
}
__device__ __forceinline__ float2 unpack2(unsigned long long r) {
    unsigned lo, hi;
    asm("mov.b64 {%0,%1}, %2;" : "=r"(lo), "=r"(hi) : "l"(r));
    return make_float2(__uint_as_float(lo), __uint_as_float(hi));
}
__device__ __forceinline__ unsigned encf(float f) {
    unsigned u = __float_as_uint(f);
    return (u & 0x80000000u) ? ~u : (u | 0x80000000u);
}
__device__ __forceinline__ float decf(unsigned u) {
    return __uint_as_float((u & 0x80000000u) ? (u & 0x7fffffffu) : ~u);
}

// -------- per-group scores: E = exp(Q@K^T - rowmax) --------------------------
#define QSTR 132
#define KSTR 130

__global__ __launch_bounds__(256) void attn_scores(
    const float* __restrict__ Q, const float* __restrict__ K, float* __restrict__ E)
{
    __shared__ float Qs[32 * QSTR];
    __shared__ float Ks[32 * KSTR];
    __shared__ float pm[128 * 17];

    int tid = threadIdx.x;
    int lane = tid & 31;
    int w = tid >> 5;
    int rg = w * 2 + (lane >> 4);
    int lc = lane & 15;
    int g = blockIdx.x;
    const float* Qg = Q + (size_t)g * 128 * 256;
    const float* Kg = K + (size_t)g * 128 * 256;

    unsigned long long acc[8][4];
#pragma unroll
    for (int i = 0; i < 8; i++) { acc[i][0]=0ULL; acc[i][1]=0ULL; acc[i][2]=0ULL; acc[i][3]=0ULL; }

    for (int k0 = 0; k0 < 256; k0 += 32) {
#pragma unroll
        for (int e = 0; e < 4; e++) {
            int idx = tid + e * 256;
            int row = idx >> 3, qq = idx & 7;
            float4 v = *(const float4*)(Qg + (size_t)row * 256 + (k0 + qq * 4));
            Qs[(qq*4+0)*QSTR + row] = v.x; Qs[(qq*4+1)*QSTR + row] = v.y;
            Qs[(qq*4+2)*QSTR + row] = v.z; Qs[(qq*4+3)*QSTR + row] = v.w;
            float4 u = *(const float4*)(Kg + (size_t)row * 256 + (k0 + qq * 4));
            Ks[(qq*4+0)*KSTR + row] = u.x; Ks[(qq*4+1)*KSTR + row] = u.y;
            Ks[(qq*4+2)*KSTR + row] = u.z; Ks[(qq*4+3)*KSTR + row] = u.w;
        }
        __syncthreads();
#pragma unroll
        for (int kk = 0; kk < 32; kk++) {
            float4 xa = *(const float4*)(Qs + kk * QSTR + rg * 8);
            float4 xb = *(const float4*)(Qs + kk * QSTR + rg * 8 + 4);
            const unsigned long long* wp = (const unsigned long long*)(Ks + kk * KSTR);
            unsigned long long b0 = wp[lc*2],      b1 = wp[lc*2 + 1];
            unsigned long long b2 = wp[32 + lc*2], b3 = wp[32 + lc*2 + 1];
            float xs8[8] = {xa.x, xa.y, xa.z, xa.w, xb.x, xb.y, xb.z, xb.w};
#pragma unroll
            for (int i = 0; i < 8; i++) {
                unsigned long long a = pack2(xs8[i], xs8[i]);
                fma2(acc[i][0], a, b0); fma2(acc[i][1], a, b1);
                fma2(acc[i][2], a, b2); fma2(acc[i][3], a, b3);
            }
        }
        __syncthreads();
    }

    float c[8][8];
    int rb = rg * 8;
#pragma unroll
    for (int i = 0; i < 8; i++) {
        float2 p0 = unpack2(acc[i][0]), p1 = unpack2(acc[i][1]);
        float2 p2 = unpack2(acc[i][2]), p3 = unpack2(acc[i][3]);
        c[i][0]=p0.x; c[i][1]=p0.y; c[i][2]=p1.x; c[i][3]=p1.y;
        c[i][4]=p2.x; c[i][5]=p2.y; c[i][6]=p3.x; c[i][7]=p3.y;
        float m = c[i][0];
#pragma unroll
        for (int j = 1; j < 8; j++) m = fmaxf(m, c[i][j]);
        pm[(rb + i) * 17 + lc] = m;
    }
    __syncthreads();
#pragma unroll
    for (int i = 0; i < 8; i++) {
        float m = pm[(rb + i) * 17];
#pragma unroll
        for (int t = 1; t < 16; t++) m = fmaxf(m, pm[(rb + i) * 17 + t]);
        size_t base = (size_t)g * 16384 + (size_t)(rb + i) * 128;
        *(float4*)(E + base + lc * 4) = make_float4(
            __expf(c[i][0]-m), __expf(c[i][1]-m), __expf(c[i][2]-m), __expf(c[i][3]-m));
        *(float4*)(E + base + 64 + lc * 4) = make_float4(
            __expf(c[i][4]-m), __expf(c[i][5]-m), __expf(c[i][6]-m), __expf(c[i][7]-m));
    }
}

// -------- per-group apply: att_half = E @ V_half -> split bf16 out -----------
#define ESTR 132
#define VSTR 132

__global__ __launch_bounds__(256) void attn_apply(
    const float* __restrict__ E, const float* __restrict__ V,
    bf16* __restrict__ Oh, bf16* __restrict__ Ol)
{
    __shared__ float Es[32 * ESTR];
    __shared__ float Vs[32 * VSTR];

    int tid = threadIdx.x;
    int lane = tid & 31;
    int w = tid >> 5;
    int rg = w * 2 + (lane >> 4);
    int lc = lane & 15;
    int g = blockIdx.x >> 1, half = blockIdx.x & 1;
    const float* Eg = E + (size_t)g * 16384;
    const float* Vg = V + (size_t)g * 128 * 256 + half * 128;

    unsigned long long acc[8][4];
#pragma unroll
    for (int i = 0; i < 8; i++) { acc[i][0]=0ULL; acc[i][1]=0ULL; acc[i][2]=0ULL; acc[i][3]=0ULL; }

    for (int k0 = 0; k0 < 128; k0 += 32) {
#pragma unroll
        for (int e = 0; e < 4; e++) {
            int idx = tid + e * 256;
            int row = idx >> 3, qq = idx & 7;
            float4 v = *(const float4*)(Eg + (size_t)row * 128 + (k0 + qq * 4));
            Es[(qq*4+0)*ESTR + row] = v.x; Es[(qq*4+1)*ESTR + row] = v.y;
            Es[(qq*4+2)*ESTR + row] = v.z; Es[(qq*4+3)*ESTR + row] = v.w;
            int kk = idx >> 5, cv = idx & 31;
            float4 u = *(const float4*)(Vg + (size_t)(k0 + kk) * 256 + cv * 4);
            *(float4*)(Vs + kk * VSTR + cv * 4) = u;
        }
        __syncthreads();
#pragma unroll
        for (int kk = 0; kk < 32; kk++) {
            float4 xa = *(const float4*)(Es + kk * ESTR + rg * 8);
            float4 xb = *(const float4*)(Es + kk * ESTR + rg * 8 + 4);
            const unsigned long long* wp = (const unsigned long long*)(Vs + kk * VSTR);
            unsigned long long b0 = wp[lc*2],      b1 = wp[lc*2 + 1];
            unsigned long long b2 = wp[32 + lc*2], b3 = wp[32 + lc*2 + 1];
            float xs8[8] = {xa.x, xa.y, xa.z, xa.w, xb.x, xb.y, xb.z, xb.w};
#pragma unroll
            for (int i = 0; i < 8; i++) {
                unsigned long long a = pack2(xs8[i], xs8[i]);
                fma2(acc[i][0], a, b0); fma2(acc[i][1], a, b1);
                fma2(acc[i][2], a, b2); fma2(acc[i][3], a, b3);
            }
        }
        __syncthreads();
    }

    int rb = rg * 8;
#pragma unroll
    for (int i = 0; i < 8; i++) {
        float2 p0 = unpack2(acc[i][0]), p1 = unpack2(acc[i][1]);
        float2 p2 = unpack2(acc[i][2]), p3 = unpack2(acc[i][3]);
        size_t base = (size_t)(g * 128 + rb + i) * 256 + half * 128;
        split_wr(Oh + base + lc * 4,      Ol + base + lc * 4,
                 make_float4(p0.x, p0.y, p1.x, p1.y));
        split_wr(Oh + base + 64 + lc * 4, Ol + base + 64 + lc * 4,
                 make_float4(p2.x, p2.y, p3.x, p3.y));
    }
}

// ---------------- segment phase ---------------------------------------------
__global__ void kinit_max(const float* __restrict__ ss, unsigned* __restrict__ mx, int n)
{
    int i = blockIdx.x * 256 + threadIdx.x;
    if (i < n) mx[i] = encf(ss[i]);
}

__global__ void kseg_max(const float* __restrict__ so, const int* __restrict__ seg,
                         unsigned* __restrict__ mx)
{
    int i = blockIdx.x * 256 + threadIdx.x;
    atomicMax(&mx[seg[i]], encf(so[i]));
}

__global__ void kout_init(const float* __restrict__ ss, const unsigned* __restrict__ mx,
                          const float* __restrict__ vs, float* __restrict__ out)
{
    int t = blockIdx.x * 256 + threadIdx.x;
    int i = t >> 6, j = t & 63;
    float e = __expf(ss[i] - decf(mx[i]));
    float4 v = ((const float4*)vs)[(size_t)i * 64 + j];
    ((float4*)out)[(size_t)i * 64 + j] = make_float4(e*v.x, e*v.y, e*v.z, e*v.w);
}

__global__ void kocc_acc(const float* __restrict__ so, const int* __restrict__ seg,
                         const unsigned* __restrict__ mx, const float* __restrict__ vo,
                         float* __restrict__ out)
{
    int t = blockIdx.x * 256 + threadIdx.x;
    int i = t >> 6, j = t & 63;
    int n = seg[i];
    float e = __expf(so[i] - decf(mx[n]));
    float4 v = ((const float4*)vo)[(size_t)i * 64 + j];
    float* p = out + (size_t)n * 256 + j * 4;
    asm volatile("red.global.add.v4.f32 [%0], {%1, %2, %3, %4};"
                 :: "l"(p), "f"(e * v.x), "f"(e * v.y), "f"(e * v.z), "f"(e * v.w)
                 : "memory");
}

__global__ void knorm(float* __restrict__ out)
{
    int row = blockIdx.x * 8 + (threadIdx.x >> 5);
    int lane = threadIdx.x & 31;
    float4* p = (float4*)(out + (size_t)row * 256);
    float4 a = p[lane], b = p[lane + 32];
    float s = a.x*a.x + a.y*a.y + a.z*a.z + a.w*a.w
            + b.x*b.x + b.y*b.y + b.z*b.z + b.w*b.w;
#pragma unroll
    for (int o = 16; o; o >>= 1) s += __shfl_xor_sync(0xffffffffu, s, o);
    float r = rsqrtf(s);
    p[lane]      = make_float4(a.x*r, a.y*r, a.z*r, a.w*r);
    p[lane + 32] = make_float4(b.x*r, b.y*r, b.z*r, b.w*r);
}

// ---------------- launch -----------------------------------------------------
extern "C" void kernel_launch(void* const* d_in, const int* in_sizes, int n_in,
                              void* d_out, int out_size)
{
    const float* xS  = (const float*)d_in[0];
    const int*   sub = (const int*)  d_in[1];
    const float* W0 = (const float*)d_in[2];
    const float* W1 = (const float*)d_in[3];
    const float* W2 = (const float*)d_in[4];
    const float* W3 = (const float*)d_in[5];
    const float* W4 = (const float*)d_in[6];
    const float* W5 = (const float*)d_in[7];
    float* out = (float*)d_out;

    float *q1, *k1, *v1, *E, *q2, *vs, *vo, *ss, *so;
    unsigned short *ath, *atl, *xh, *xl, *wh, *wl;
    unsigned* mx;
    cudaGetSymbolAddress((void**)&q1,  g_q1);
    cudaGetSymbolAddress((void**)&k1,  g_k1);
    cudaGetSymbolAddress((void**)&v1,  g_v1);
    cudaGetSymbolAddress((void**)&E,   g_E);
    cudaGetSymbolAddress((void**)&ath, g_ath);
    cudaGetSymbolAddress((void**)&atl, g_atl);
    cudaGetSymbolAddress((void**)&xh,  g_xh);
    cudaGetSymbolAddress((void**)&xl,  g_xl);
    cudaGetSymbolAddress((void**)&wh,  g_wh);
    cudaGetSymbolAddress((void**)&wl,  g_wl);
    cudaGetSymbolAddress((void**)&q2,  g_q2);
    cudaGetSymbolAddress((void**)&vs,  g_vs);
    cudaGetSymbolAddress((void**)&vo,  g_vo);
    cudaGetSymbolAddress((void**)&ss,  g_ss);
    cudaGetSymbolAddress((void**)&so,  g_so);
    cudaGetSymbolAddress((void**)&mx,  g_mx);

    cudaFuncSetAttribute(mma_proj_tc, cudaFuncAttributeMaxDynamicSharedMemorySize, SMEMTC);

    bf16* XH = (bf16*)xh;  bf16* XL = (bf16*)xl;
    bf16* AH = (bf16*)ath; bf16* AL = (bf16*)atl;
    bf16* WH[6]; bf16* WL[6];
    for (int i = 0; i < 6; i++) { WH[i] = (bf16*)(wh + i * 65536); WL[i] = (bf16*)(wl + i * 65536); }

    int nTilesN = (DN + 127) / 128;

    // #1, #2: input splits
    ksplit<<<DN * 64 / 256, 256>>>(xS, XH, XL, DN * 64);
    ksplit6<<<384, 256>>>(W0, W1, W2, W3, W4, W5, WH[0], WL[0]);

    // #3-#5: phase-1 projections (gathered)
    mma_proj_tc<<<DM / 128, 256, SMEMTC>>>(XH, XL, sub, WH[0], WL[0], q1, DM,
                                           nullptr, nullptr, nullptr);
    mma_proj_tc<<<DM / 128, 256, SMEMTC>>>(XH, XL, sub, WH[1], WL[1], k1, DM,
                                           nullptr, nullptr, nullptr);
    mma_proj_tc<<<DM / 128, 256, SMEMTC>>>(XH, XL, sub, WH[2], WL[2], v1, DM,
                                           nullptr, nullptr, nullptr);

    // #6-#8: phase-2 X projections (independent of attention; #6 gets profiled)
    mma_proj_tc<<<nTilesN, 256, SMEMTC>>>(XH, XL, nullptr, WH[3], WL[3], q2, DN,
                                          nullptr, nullptr, nullptr);
    mma_proj_tc<<<nTilesN, 256, SMEMTC>>>(XH, XL, nullptr, WH[5], WL[5], vs, DN,
                                          nullptr, nullptr, nullptr);
    mma_proj_tc<<<nTilesN, 256, SMEMTC>>>(XH, XL, nullptr, WH[4], WL[4],
                                          nullptr, DN, q2, nullptr, ss);

    // #9-#10: subset attention
    attn_scores<<<DG, 256>>>(q1, k1, E);
    attn_apply<<<DG * 2, 256>>>(E, v1, AH, AL);

    // #11-#12: att projections (dot-fused ko, plus vo)
    mma_proj_tc<<<DM / 128, 256, SMEMTC>>>(AH, AL, nullptr, WH[4], WL[4],
                                           nullptr, DM, q2, sub, so);
    mma_proj_tc<<<DM / 128, 256, SMEMTC>>>(AH, AL, nullptr, WH[5], WL[5], vo, DM,
                                           nullptr, nullptr, nullptr);

    // segment softmax aggregation
    kinit_max<<<(DN + 255) / 256, 256>>>(ss, mx, DN);
    kseg_max<<<DM / 256, 256>>>(so, sub, mx);
    kout_init<<<DN * 64 / 256, 256>>>(ss, mx, vs, out);
    kocc_acc<<<DM * 64 / 256, 256>>>(so, sub, mx, vo, out);
    knorm<<<DN / 8, 256>>>(out);
}

// round 15
// speedup vs baseline: 1.9871x; 1.0069x over previous
#include <cuda_runtime.h>
#include <cuda_bf16.h>
#include <cstdint>

#define DN 200000
#define DDIM 256
#define DG 1024
#define DS 128
#define DM (DG*DS)

typedef __nv_bfloat16 bf16;

// ---------------- scratch: __device__ globals (no allocation allowed) --------
__device__ float          g_q1[(size_t)DM*DDIM];
__device__ float          g_k1[(size_t)DM*DDIM];
__device__ float          g_v1[(size_t)DM*DDIM];
__device__ float          g_E [(size_t)DG*DS*DS];
__device__ unsigned short g_ath[(size_t)DM*DDIM];   // att hi (bf16 bits)
__device__ unsigned short g_atl[(size_t)DM*DDIM];   // att lo
__device__ unsigned short g_xh [(size_t)DN*DDIM];   // xS hi
__device__ unsigned short g_xl [(size_t)DN*DDIM];   // xS lo
__device__ unsigned short g_wh [6*65536];           // weights hi
__device__ unsigned short g_wl [6*65536];           // weights lo
__device__ float          g_q2[(size_t)DN*DDIM];
__device__ float          g_vs[(size_t)DN*DDIM];
__device__ float          g_vo[(size_t)DM*DDIM];
__device__ float          g_ss[DN];
__device__ float          g_so[DM];
__device__ unsigned       g_mx[DN];

// ---------------- fp32 -> (hi,lo) bf16 split ---------------------------------
__device__ __forceinline__ void split_wr(bf16* H, bf16* L, float4 v) {
    bf16 h0 = __float2bfloat16(v.x), h1 = __float2bfloat16(v.y);
    bf16 h2 = __float2bfloat16(v.z), h3 = __float2bfloat16(v.w);
    bf16 l0 = __float2bfloat16(v.x - __bfloat162float(h0));
    bf16 l1 = __float2bfloat16(v.y - __bfloat162float(h1));
    bf16 l2 = __float2bfloat16(v.z - __bfloat162float(h2));
    bf16 l3 = __float2bfloat16(v.w - __bfloat162float(h3));
    ((__nv_bfloat162*)H)[0] = __halves2bfloat162(h0, h1);
    ((__nv_bfloat162*)H)[1] = __halves2bfloat162(h2, h3);
    ((__nv_bfloat162*)L)[0] = __halves2bfloat162(l0, l1);
    ((__nv_bfloat162*)L)[1] = __halves2bfloat162(l2, l3);
}

__global__ void ksplit(const float* __restrict__ x, bf16* __restrict__ hi,
                       bf16* __restrict__ lo, int n4) {
    int i = blockIdx.x * 256 + threadIdx.x;
    if (i < n4)
        split_wr(hi + 4 * (size_t)i, lo + 4 * (size_t)i, ((const float4*)x)[i]);
}

// all six 256x256 weights in one launch: 6*16384 float4 elements
__global__ void ksplit6(const float* w0, const float* w1, const float* w2,
                        const float* w3, const float* w4, const float* w5,
                        bf16* __restrict__ hi, bf16* __restrict__ lo) {
    int i = blockIdx.x * 256 + threadIdx.x;   // 0 .. 98303
    int which = i >> 14, off = i & 16383;
    const float* w = (which == 0) ? w0 : (which == 1) ? w1 : (which == 2) ? w2
                   : (which == 3) ? w3 : (which == 4) ? w4 : w5;
    split_wr(hi + 4 * (size_t)i, lo + 4 * (size_t)i, ((const float4*)w)[off]);
}

// ---------------- mma.sync bf16 GEMM + proj, cp.async + ldmatrix -------------
// C[128,256] = proj(X@W^T); 3-term split Ahi*Bhi + Ahi*Blo + Alo*Bhi.
// Block 256 thr (8 warps), warp tile 64x64 (wm=wid&1, wn=wid>>1), K chunks 32.
// Optional fused dot: dotout[row] = C_row . dotq[dotg?dotg[row]:row].
__device__ __forceinline__ void mma16816(float* d, const unsigned* a,
                                         unsigned b0, unsigned b1) {
    asm volatile(
        "mma.sync.aligned.m16n8k16.row.col.f32.bf16.bf16.f32 "
        "{%0,%1,%2,%3}, {%4,%5,%6,%7}, {%8,%9}, {%0,%1,%2,%3};"
        : "+f"(d[0]), "+f"(d[1]), "+f"(d[2]), "+f"(d[3])
        : "r"(a[0]), "r"(a[1]), "r"(a[2]), "r"(a[3]), "r"(b0), "r"(b1));
}
__device__ __forceinline__ void ldsm4(unsigned& r0, unsigned& r1,
                                      unsigned& r2, unsigned& r3, uint32_t addr) {
    asm volatile("ldmatrix.sync.aligned.m8n8.x4.shared.b16 {%0,%1,%2,%3}, [%4];"
        : "=r"(r0), "=r"(r1), "=r"(r2), "=r"(r3) : "r"(addr));
}
__device__ __forceinline__ void cpa16(uint32_t dst, const void* src) {
    asm volatile("cp.async.cg.shared.global [%0], [%1], 16;"
                 :: "r"(dst), "l"(src));
}
#define CP_COMMIT() asm volatile("cp.async.commit_group;")
#define CP_WAIT1()  asm volatile("cp.async.wait_group 1;")
#define CP_WAIT0()  asm volatile("cp.async.wait_group 0;")

#define ASTR 40                 // bf16 stride: 80B rows, ldmatrix conflict-free
#define STG_BYTES 61440         // AH 10240 | AL 10240 | BH 20480 | BL 20480
#define OFF_AL 10240
#define OFF_BH 20480
#define OFF_RN (2*STG_BYTES)
#define OFF_RD (OFF_RN + 512)
#define OFF_RS (OFF_RD + 512)
#define SMEMTC (OFF_RS + 512)

__global__ void __launch_bounds__(256) mma_proj_tc(
    const bf16* __restrict__ Ahi, const bf16* __restrict__ Alo,
    const int* __restrict__ gidx,
    const bf16* __restrict__ Bhi, const bf16* __restrict__ Blo,
    float* __restrict__ C, int nrows,
    const float* __restrict__ dotq, const int* __restrict__ dotg,
    float* __restrict__ dotout)
{
    extern __shared__ __align__(16) char smc[];
    float* rn   = (float*)(smc + OFF_RN);
    float* rd   = (float*)(smc + OFF_RD);
    int*   rsrc = (int*)  (smc + OFF_RS);
    uint32_t sbase = (uint32_t)__cvta_generic_to_shared(smc);

    int tid = threadIdx.x;
    int wid = tid >> 5, lane = tid & 31;
    int wm = wid & 1, wn = wid >> 1;           // wm: 2x64 rows, wn: 4x64 cols
    int g  = lane >> 2, tg = lane & 3;
    int r0 = blockIdx.x * 128;

    if (tid < 128) {
        int sr = r0 + tid;
        if (sr >= nrows) sr = nrows - 1;
        rsrc[tid] = gidx ? gidx[sr] : sr;
        rn[tid] = 0.f;
        rd[tid] = 0.f;
    }
    __syncthreads();

    // fill roles: each thread owns one 16B segment column (seg = tid&3)
    int arow0 = tid >> 2, seg = tid & 3;       // arow0: 0..63
    size_t ab0 = (size_t)rsrc[arow0]      * 256 + seg * 8;
    size_t ab1 = (size_t)rsrc[arow0 + 64] * 256 + seg * 8;
    uint32_t dA0 = sbase + arow0 * 80 + seg * 16;
    uint32_t dA1 = sbase + (arow0 + 64) * 80 + seg * 16;

    // ldmatrix per-lane byte offsets (within a tile, ASTR*2 = 80B rows)
    // A: m = lane>>3: row = (m&1)*8 + (lane&7), colhalf = m>>1 (k 0/8)
    uint32_t aoff = (uint32_t)((((lane >> 3) & 1) * 8 + (lane & 7)) * 80
                               + (lane >> 4) * 16);
    // B: m = lane>>3: row = (m>>1)*8 + (lane&7), k-half = m&1
    uint32_t boff = (uint32_t)((((lane >> 3) >> 1) * 8 + (lane & 7)) * 80
                               + ((lane >> 3) & 1) * 16);

    float acc[4][8][4];
#pragma unroll
    for (int mt = 0; mt < 4; mt++)
#pragma unroll
        for (int nt = 0; nt < 8; nt++)
#pragma unroll
            for (int j = 0; j < 4; j++) acc[mt][nt][j] = 0.f;

    // prefetch chunk 0 into stage 0
    {
        cpa16(dA0, Ahi + ab0); cpa16(dA0 + OFF_AL, Alo + ab0);
        cpa16(dA1, Ahi + ab1); cpa16(dA1 + OFF_AL, Alo + ab1);
#pragma unroll
        for (int e = 0; e < 4; e++) {
            int row = arow0 + e * 64;
            uint32_t dB = sbase + OFF_BH + row * 80 + seg * 16;
            cpa16(dB, Bhi + (size_t)row * 256 + seg * 8);
            cpa16(dB + 20480, Blo + (size_t)row * 256 + seg * 8);
        }
        CP_COMMIT();
    }

    for (int c = 0; c < 8; c++) {
        if (c < 7) {
            int k1 = (c + 1) * 32;
            uint32_t so = ((c + 1) & 1) * STG_BYTES;
            cpa16(dA0 + so, Ahi + ab0 + k1); cpa16(dA0 + OFF_AL + so, Alo + ab0 + k1);
            cpa16(dA1 + so, Ahi + ab1 + k1); cpa16(dA1 + OFF_AL + so, Alo + ab1 + k1);
#pragma unroll
            for (int e = 0; e < 4; e++) {
                int row = arow0 + e * 64;
                uint32_t dB = sbase + OFF_BH + row * 80 + seg * 16 + so;
                cpa16(dB, Bhi + (size_t)row * 256 + seg * 8 + k1);
                cpa16(dB + 20480, Blo + (size_t)row * 256 + seg * 8 + k1);
            }
            CP_COMMIT();
            CP_WAIT1();
        } else {
            CP_WAIT0();
        }
        __syncthreads();

        uint32_t stg = sbase + (c & 1) * STG_BYTES;
        uint32_t aH = stg + (uint32_t)(wm * 64) * 80 + aoff;           // AsH
        uint32_t aL = aH + OFF_AL;                                     // AsL
        uint32_t bH = stg + OFF_BH + (uint32_t)(wn * 64) * 80 + boff;  // BsH
        uint32_t bL = bH + 20480;                                      // BsL

#pragma unroll
        for (int ks = 0; ks < 2; ks++) {
            uint32_t kb = (uint32_t)(ks * 32);   // 16 bf16 = 32 bytes
            unsigned af[4][4];
#pragma unroll
            for (int mt = 0; mt < 4; mt++)
                ldsm4(af[mt][0], af[mt][1], af[mt][2], af[mt][3],
                      aH + (uint32_t)(mt * 1280) + kb);
            unsigned bh[8][2], bl[8][2];
#pragma unroll
            for (int np = 0; np < 4; np++) {
                ldsm4(bh[2*np][0], bh[2*np][1], bh[2*np+1][0], bh[2*np+1][1],
                      bH + (uint32_t)(np * 1280) + kb);
                ldsm4(bl[2*np][0], bl[2*np][1], bl[2*np+1][0], bl[2*np+1][1],
                      bL + (uint32_t)(np * 1280) + kb);
            }
            // term1: Ahi * Bhi
#pragma unroll
            for (int nt = 0; nt < 8; nt++)
#pragma unroll
                for (int mt = 0; mt < 4; mt++)
                    mma16816(acc[mt][nt], af[mt], bh[nt][0], bh[nt][1]);
            // term2: Ahi * Blo
#pragma unroll
            for (int nt = 0; nt < 8; nt++)
#pragma unroll
                for (int mt = 0; mt < 4; mt++)
                    mma16816(acc[mt][nt], af[mt], bl[nt][0], bl[nt][1]);
            // term3: Alo * Bhi (reload A frags into af)
#pragma unroll
            for (int mt = 0; mt < 4; mt++)
                ldsm4(af[mt][0], af[mt][1], af[mt][2], af[mt][3],
                      aL + (uint32_t)(mt * 1280) + kb);
#pragma unroll
            for (int nt = 0; nt < 8; nt++)
#pragma unroll
                for (int mt = 0; mt < 4; mt++)
                    mma16816(acc[mt][nt], af[mt], bh[nt][0], bh[nt][1]);
        }
        __syncthreads();
    }

    // ---- projection: per-row sumsq across 256 cols via smem atomics ----
#pragma unroll
    for (int mt = 0; mt < 4; mt++) {
        float s0 = 0.f, s1 = 0.f;
#pragma unroll
        for (int nt = 0; nt < 8; nt++) {
            s0 += acc[mt][nt][0] * acc[mt][nt][0] + acc[mt][nt][1] * acc[mt][nt][1];
            s1 += acc[mt][nt][2] * acc[mt][nt][2] + acc[mt][nt][3] * acc[mt][nt][3];
        }
        s0 += __shfl_xor_sync(0xffffffffu, s0, 1);
        s0 += __shfl_xor_sync(0xffffffffu, s0, 2);
        s1 += __shfl_xor_sync(0xffffffffu, s1, 1);
        s1 += __shfl_xor_sync(0xffffffffu, s1, 2);
        if (tg == 0) {
            atomicAdd(&rn[wm * 64 + mt * 16 + g], s0);
            atomicAdd(&rn[wm * 64 + mt * 16 + 8 + g], s1);
        }
    }
    __syncthreads();

#pragma unroll
    for (int mt = 0; mt < 4; mt++) {
        int rl = wm * 64 + mt * 16 + g;
        float sa = rsqrtf(rn[rl]);
        float sb = rsqrtf(rn[rl + 8]);
        bool oka = (r0 + rl) < nrows;
        bool okb = (r0 + rl + 8) < nrows;
#pragma unroll
        for (int nt = 0; nt < 8; nt++) {
            acc[mt][nt][0] *= sa; acc[mt][nt][1] *= sa;
            acc[mt][nt][2] *= sb; acc[mt][nt][3] *= sb;
        }
        if (C) {
            float* ca = C + (size_t)(r0 + rl) * 256;
            float* cb = C + (size_t)(r0 + rl + 8) * 256;
#pragma unroll
            for (int nt = 0; nt < 8; nt++) {
                int col = wn * 64 + nt * 8 + tg * 2;
                if (oka) *(float2*)(ca + col) =
                    make_float2(acc[mt][nt][0], acc[mt][nt][1]);
                if (okb) *(float2*)(cb + col) =
                    make_float2(acc[mt][nt][2], acc[mt][nt][3]);
            }
        }
        if (dotq) {
            float da = 0.f, db = 0.f;
            if (oka) {
                int qa = dotg ? dotg[r0 + rl] : (r0 + rl);
                const float* qp = dotq + (size_t)qa * 256;
#pragma unroll
                for (int nt = 0; nt < 8; nt++) {
                    float2 q = *(const float2*)(qp + wn * 64 + nt * 8 + tg * 2);
                    da += acc[mt][nt][0] * q.x + acc[mt][nt][1] * q.y;
                }
            }
            if (okb) {
                int qb = dotg ? dotg[r0 + rl + 8] : (r0 + rl + 8);
                const float* qp = dotq + (size_t)qb * 256;
#pragma unroll
                for (int nt = 0; nt < 8; nt++) {
                    float2 q = *(const float2*)(qp + wn * 64 + nt * 8 + tg * 2);
                    db += acc[mt][nt][2] * q.x + acc[mt][nt][3] * q.y;
                }
            }
            da += __shfl_xor_sync(0xffffffffu, da, 1);
            da += __shfl_xor_sync(0xffffffffu, da, 2);
            db += __shfl_xor_sync(0xffffffffu, db, 1);
            db += __shfl_xor_sync(0xffffffffu, db, 2);
            if (tg == 0) {
                atomicAdd(&rd[rl], da);
                atomicAdd(&rd[rl + 8], db);
            }
        }
    }
    if (dotq) {
        __syncthreads();
        if (tid < 128 && (r0 + tid) < nrows) dotout[r0 + tid] = rd[tid];
    }
}

// ---------------- packed f32x2 helpers (FFMA2 path, attention) ---------------
__device__ __forceinline__ unsigned long long pack2(float x, float y) {
    unsigned long long r;
    asm("mov.b64 %0, {%1,%2};" : "=l"(r)
        : "r"(__float_as_uint(x)), "r"(__float_as_uint(y)));
    return r;
}
__device__ __forceinline__ void fma2(unsigned long long& d,
                                     unsigned long long a, unsigned long long b) {
    asm("fma.rn.f32x2 %0, %1, %2, %0;" : "+l"(d) : "l"(a), "l"(b));
}
__device__ __forceinline__ float2 unpack2(unsigned long long r) {
    unsigned lo, hi;
    asm("mov.b64 {%0,%1}, %2;" : "=r"(lo), "=r"(hi) : "l"(r));
    return make_float2(__uint_as_float(lo), __uint_as_float(hi));
}
__device__ __forceinline__ unsigned encf(float f) {
    unsigned u = __float_as_uint(f);
    return (u & 0x80000000u) ? ~u : (u | 0x80000000u);
}
__device__ __forceinline__ float decf(unsigned u) {
    return __uint_as_float((u & 0x80000000u) ? (u & 0x7fffffffu) : ~u);
}

// -------- per-group scores: E = exp(Q@K^T - rowmax) --------------------------
#define QSTR 132
#define KSTR 130

__global__ __launch_bounds__(256) void attn_scores(
    const float* __restrict__ Q, const float* __restrict__ K, float* __restrict__ E)
{
    __shared__ float Qs[32 * QSTR];
    __shared__ float Ks[32 * KSTR];
    __shared__ float pm[128 * 17];

    int tid = threadIdx.x;
    int lane = tid & 31;
    int w = tid >> 5;
    int rg = w * 2 + (lane >> 4);
    int lc = lane & 15;
    int g = blockIdx.x;
    const float* Qg = Q + (size_t)g * 128 * 256;
    const float* Kg = K + (size_t)g * 128 * 256;

    unsigned long long acc[8][4];
#pragma unroll
    for (int i = 0; i < 8; i++) { acc[i][0]=0ULL; acc[i][1]=0ULL; acc[i][2]=0ULL; acc[i][3]=0ULL; }

    for (int k0 = 0; k0 < 256; k0 += 32) {
#pragma unroll
        for (int e = 0; e < 4; e++) {
            int idx = tid + e * 256;
            int row = idx >> 3, qq = idx & 7;
            float4 v = *(const float4*)(Qg + (size_t)row * 256 + (k0 + qq * 4));
            Qs[(qq*4+0)*QSTR + row] = v.x; Qs[(qq*4+1)*QSTR + row] = v.y;
            Qs[(qq*4+2)*QSTR + row] = v.z; Qs[(qq*4+3)*QSTR + row] = v.w;
            float4 u = *(const float4*)(Kg + (size_t)row * 256 + (k0 + qq * 4));
            Ks[(qq*4+0)*KSTR + row] = u.x; Ks[(qq*4+1)*KSTR + row] = u.y;
            Ks[(qq*4+2)*KSTR + row] = u.z; Ks[(qq*4+3)*KSTR + row] = u.w;
        }
        __syncthreads();
#pragma unroll
        for (int kk = 0; kk < 32; kk++) {
            float4 xa = *(const float4*)(Qs + kk * QSTR + rg * 8);
            float4 xb = *(const float4*)(Qs + kk * QSTR + rg * 8 + 4);
            const unsigned long long* wp = (const unsigned long long*)(Ks + kk * KSTR);
            unsigned long long b0 = wp[lc*2],      b1 = wp[lc*2 + 1];
            unsigned long long b2 = wp[32 + lc*2], b3 = wp[32 + lc*2 + 1];
            float xs8[8] = {xa.x, xa.y, xa.z, xa.w, xb.x, xb.y, xb.z, xb.w};
#pragma unroll
            for (int i = 0; i < 8; i++) {
                unsigned long long a = pack2(xs8[i], xs8[i]);
                fma2(acc[i][0], a, b0); fma2(acc[i][1], a, b1);
                fma2(acc[i][2], a, b2); fma2(acc[i][3], a, b3);
            }
        }
        __syncthreads();
    }

    float c[8][8];
    int rb = rg * 8;
#pragma unroll
    for (int i = 0; i < 8; i++) {
        float2 p0 = unpack2(acc[i][0]), p1 = unpack2(acc[i][1]);
        float2 p2 = unpack2(acc[i][2]), p3 = unpack2(acc[i][3]);
        c[i][0]=p0.x; c[i][1]=p0.y; c[i][2]=p1.x; c[i][3]=p1.y;
        c[i][4]=p2.x; c[i][5]=p2.y; c[i][6]=p3.x; c[i][7]=p3.y;
        float m = c[i][0];
#pragma unroll
        for (int j = 1; j < 8; j++) m = fmaxf(m, c[i][j]);
        pm[(rb + i) * 17 + lc] = m;
    }
    __syncthreads();
#pragma unroll
    for (int i = 0; i < 8; i++) {
        float m = pm[(rb + i) * 17];
#pragma unroll
        for (int t = 1; t < 16; t++) m = fmaxf(m, pm[(rb + i) * 17 + t]);
        size_t base = (size_t)g * 16384 + (size_t)(rb + i) * 128;
        *(float4*)(E + base + lc * 4) = make_float4(
            __expf(c[i][0]-m), __expf(c[i][1]-m), __expf(c[i][2]-m), __expf(c[i][3]-m));
        *(float4*)(E + base + 64 + lc * 4) = make_float4(
            __expf(c[i][4]-m), __expf(c[i][5]-m), __expf(c[i][6]-m), __expf(c[i][7]-m));
    }
}

// -------- per-group apply: att_half = E @ V_half -> split bf16 out -----------
#define ESTR 132
#define VSTR 132

__global__ __launch_bounds__(256) void attn_apply(
    const float* __restrict__ E, const float* __restrict__ V,
    bf16* __restrict__ Oh, bf16* __restrict__ Ol)
{
    __shared__ float Es[32 * ESTR];
    __shared__ float Vs[32 * VSTR];

    int tid = threadIdx.x;
    int lane = tid & 31;
    int w = tid >> 5;
    int rg = w * 2 + (lane >> 4);
    int lc = lane & 15;
    int g = blockIdx.x >> 1, half = blockIdx.x & 1;
    const float* Eg = E + (size_t)g * 16384;
    const float* Vg = V + (size_t)g * 128 * 256 + half * 128;

    unsigned long long acc[8][4];
#pragma unroll
    for (int i = 0; i < 8; i++) { acc[i][0]=0ULL; acc[i][1]=0ULL; acc[i][2]=0ULL; acc[i][3]=0ULL; }

    for (int k0 = 0; k0 < 128; k0 += 32) {
#pragma unroll
        for (int e = 0; e < 4; e++) {
            int idx = tid + e * 256;
            int row = idx >> 3, qq = idx & 7;
            float4 v = *(const float4*)(Eg + (size_t)row * 128 + (k0 + qq * 4));
            Es[(qq*4+0)*ESTR + row] = v.x; Es[(qq*4+1)*ESTR + row] = v.y;
            Es[(qq*4+2)*ESTR + row] = v.z; Es[(qq*4+3)*ESTR + row] = v.w;
            int kk = idx >> 5, cv = idx & 31;
            float4 u = *(const float4*)(Vg + (size_t)(k0 + kk) * 256 + cv * 4);
            *(float4*)(Vs + kk * VSTR + cv * 4) = u;
        }
        __syncthreads();
#pragma unroll
        for (int kk = 0; kk < 32; kk++) {
            float4 xa = *(const float4*)(Es + kk * ESTR + rg * 8);
            float4 xb = *(const float4*)(Es + kk * ESTR + rg * 8 + 4);
            const unsigned long long* wp = (const unsigned long long*)(Vs + kk * VSTR);
            unsigned long long b0 = wp[lc*2],      b1 = wp[lc*2 + 1];
            unsigned long long b2 = wp[32 + lc*2], b3 = wp[32 + lc*2 + 1];
            float xs8[8] = {xa.x, xa.y, xa.z, xa.w, xb.x, xb.y, xb.z, xb.w};
#pragma unroll
            for (int i = 0; i < 8; i++) {
                unsigned long long a = pack2(xs8[i], xs8[i]);
                fma2(acc[i][0], a, b0); fma2(acc[i][1], a, b1);
                fma2(acc[i][2], a, b2); fma2(acc[i][3], a, b3);
            }
        }
        __syncthreads();
    }

    int rb = rg * 8;
#pragma unroll
    for (int i = 0; i < 8; i++) {
        float2 p0 = unpack2(acc[i][0]), p1 = unpack2(acc[i][1]);
        float2 p2 = unpack2(acc[i][2]), p3 = unpack2(acc[i][3]);
        size_t base = (size_t)(g * 128 + rb + i) * 256 + half * 128;
        split_wr(Oh + base + lc * 4,      Ol + base + lc * 4,
                 make_float4(p0.x, p0.y, p1.x, p1.y));
        split_wr(Oh + base + 64 + lc * 4, Ol + base + 64 + lc * 4,
                 make_float4(p2.x, p2.y, p3.x, p3.y));
    }
}

// ---------------- segment phase ---------------------------------------------
__global__ void kinit_max(const float* __restrict__ ss, unsigned* __restrict__ mx, int n)
{
    int i = blockIdx.x * 256 + threadIdx.x;
    if (i < n) mx[i] = encf(ss[i]);
}

__global__ void kseg_max(const float* __restrict__ so, const int* __restrict__ seg,
                         unsigned* __restrict__ mx)
{
    int i = blockIdx.x * 256 + threadIdx.x;
    atomicMax(&mx[seg[i]], encf(so[i]));
}

__global__ void kout_init(const float* __restrict__ ss, const unsigned* __restrict__ mx,
                          const float* __restrict__ vs, float* __restrict__ out)
{
    int t = blockIdx.x * 256 + threadIdx.x;
    int i = t >> 6, j = t & 63;
    float e = __expf(ss[i] - decf(mx[i]));
    float4 v = ((const float4*)vs)[(size_t)i * 64 + j];
    ((float4*)out)[(size_t)i * 64 + j] = make_float4(e*v.x, e*v.y, e*v.z, e*v.w);
}

__global__ void kocc_acc(const float* __restrict__ so, const int* __restrict__ seg,
                         const unsigned* __restrict__ mx, const float* __restrict__ vo,
                         float* __restrict__ out)
{
    int t = blockIdx.x * 256 + threadIdx.x;
    int i = t >> 6, j = t & 63;
    int n = seg[i];
    float e = __expf(so[i] - decf(mx[n]));
    float4 v = ((const float4*)vo)[(size_t)i * 64 + j];
    float* p = out + (size_t)n * 256 + j * 4;
    asm volatile("red.global.add.v4.f32 [%0], {%1, %2, %3, %4};"
                 :: "l"(p), "f"(e * v.x), "f"(e * v.y), "f"(e * v.z), "f"(e * v.w)
                 : "memory");
}

__global__ void knorm(float* __restrict__ out)
{
    int row = blockIdx.x * 8 + (threadIdx.x >> 5);
    int lane = threadIdx.x & 31;
    float4* p = (float4*)(out + (size_t)row * 256);
    float4 a = p[lane], b = p[lane + 32];
    float s = a.x*a.x + a.y*a.y + a.z*a.z + a.w*a.w
            + b.x*b.x + b.y*b.y + b.z*b.z + b.w*b.w;
#pragma unroll
    for (int o = 16; o; o >>= 1) s += __shfl_xor_sync(0xffffffffu, s, o);
    float r = rsqrtf(s);
    p[lane]      = make_float4(a.x*r, a.y*r, a.z*r, a.w*r);
    p[lane + 32] = make_float4(b.x*r, b.y*r, b.z*r, b.w*r);
}

// ---------------- launch -----------------------------------------------------
extern "C" void kernel_launch(void* const* d_in, const int* in_sizes, int n_in,
                              void* d_out, int out_size)
{
    const float* xS  = (const float*)d_in[0];
    const int*   sub = (const int*)  d_in[1];
    const float* W0 = (const float*)d_in[2];
    const float* W1 = (const float*)d_in[3];
    const float* W2 = (const float*)d_in[4];
    const float* W3 = (const float*)d_in[5];
    const float* W4 = (const float*)d_in[6];
    const float* W5 = (const float*)d_in[7];
    float* out = (float*)d_out;

    float *q1, *k1, *v1, *E, *q2, *vs, *vo, *ss, *so;
    unsigned short *ath, *atl, *xh, *xl, *wh, *wl;
    unsigned* mx;
    cudaGetSymbolAddress((void**)&q1,  g_q1);
    cudaGetSymbolAddress((void**)&k1,  g_k1);
    cudaGetSymbolAddress((void**)&v1,  g_v1);
    cudaGetSymbolAddress((void**)&E,   g_E);
    cudaGetSymbolAddress((void**)&ath, g_ath);
    cudaGetSymbolAddress((void**)&atl, g_atl);
    cudaGetSymbolAddress((void**)&xh,  g_xh);
    cudaGetSymbolAddress((void**)&xl,  g_xl);
    cudaGetSymbolAddress((void**)&wh,  g_wh);
    cudaGetSymbolAddress((void**)&wl,  g_wl);
    cudaGetSymbolAddress((void**)&q2,  g_q2);
    cudaGetSymbolAddress((void**)&vs,  g_vs);
    cudaGetSymbolAddress((void**)&vo,  g_vo);
    cudaGetSymbolAddress((void**)&ss,  g_ss);
    cudaGetSymbolAddress((void**)&so,  g_so);
    cudaGetSymbolAddress((void**)&mx,  g_mx);

    cudaFuncSetAttribute(mma_proj_tc, cudaFuncAttributeMaxDynamicSharedMemorySize, SMEMTC);

    bf16* XH = (bf16*)xh;  bf16* XL = (bf16*)xl;
    bf16* AH = (bf16*)ath; bf16* AL = (bf16*)atl;
    bf16* WH[6]; bf16* WL[6];
    for (int i = 0; i < 6; i++) { WH[i] = (bf16*)(wh + i * 65536); WL[i] = (bf16*)(wl + i * 65536); }

    int nTilesN = (DN + 127) / 128;

    // #1, #2: input splits
    ksplit<<<DN * 64 / 256, 256>>>(xS, XH, XL, DN * 64);
    ksplit6<<<384, 256>>>(W0, W1, W2, W3, W4, W5, WH[0], WL[0]);

    // #3-#5: phase-1 projections (gathered)
    mma_proj_tc<<<DM / 128, 256, SMEMTC>>>(XH, XL, sub, WH[0], WL[0], q1, DM,
                                           nullptr, nullptr, nullptr);
    mma_proj_tc<<<DM / 128, 256, SMEMTC>>>(XH, XL, sub, WH[1], WL[1], k1, DM,
                                           nullptr, nullptr, nullptr);
    mma_proj_tc<<<DM / 128, 256, SMEMTC>>>(XH, XL, sub, WH[2], WL[2], v1, DM,
                                           nullptr, nullptr, nullptr);

    // #6-#8: phase-2 X projections (independent of attention; #6 gets profiled)
    mma_proj_tc<<<nTilesN, 256, SMEMTC>>>(XH, XL, nullptr, WH[3], WL[3], q2, DN,
                                          nullptr, nullptr, nullptr);
    mma_proj_tc<<<nTilesN, 256, SMEMTC>>>(XH, XL, nullptr, WH[5], WL[5], vs, DN,
                                          nullptr, nullptr, nullptr);
    mma_proj_tc<<<nTilesN, 256, SMEMTC>>>(XH, XL, nullptr, WH[4], WL[4],
                                          nullptr, DN, q2, nullptr, ss);

    // #9-#10: subset attention
    attn_scores<<<DG, 256>>>(q1, k1, E);
    attn_apply<<<DG * 2, 256>>>(E, v1, AH, AL);

    // #11-#12: att projections (dot-fused ko, plus vo)
    mma_proj_tc<<<DM / 128, 256, SMEMTC>>>(AH, AL, nullptr, WH[4], WL[4],
                                           nullptr, DM, q2, sub, so);
    mma_proj_tc<<<DM / 128, 256, SMEMTC>>>(AH, AL, nullptr, WH[5], WL[5], vo, DM,
                                           nullptr, nullptr, nullptr);

    // segment softmax aggregation
    kinit_max<<<(DN + 255) / 256, 256>>>(ss, mx, DN);
    kseg_max<<<DM / 256, 256>>>(so, sub, mx);
    kout_init<<<DN * 64 / 256, 256>>>(ss, mx, vs, out);
    kocc_acc<<<DM * 64 / 256, 256>>>(so, sub, mx, vo, out);
    knorm<<<DN / 8, 256>>>(out);
}

// round 17
// speedup vs baseline: 2.0657x; 1.0396x over previous
#include <cuda_runtime.h>
#include <cuda_bf16.h>
#include <cstdint>

#define DN 200000
#define DDIM 256
#define DG 1024
#define DS 128
#define DM (DG*DS)

typedef __nv_bfloat16 bf16;

// ---------------- scratch: __device__ globals (no allocation allowed) --------
__device__ float          g_q1[(size_t)DM*DDIM];
__device__ float          g_k1[(size_t)DM*DDIM];
__device__ float          g_v1[(size_t)DM*DDIM];
__device__ float          g_E [(size_t)DG*DS*DS];
__device__ unsigned short g_ath[(size_t)DM*DDIM];   // att hi (bf16 bits)
__device__ unsigned short g_atl[(size_t)DM*DDIM];   // att lo
__device__ unsigned short g_xh [(size_t)DN*DDIM];   // xS hi
__device__ unsigned short g_xl [(size_t)DN*DDIM];   // xS lo
__device__ unsigned short g_wh [6*65536];           // weights hi
__device__ unsigned short g_wl [6*65536];           // weights lo
__device__ float          g_q2[(size_t)DN*DDIM];
__device__ float          g_vs[(size_t)DN*DDIM];
__device__ float          g_vo[(size_t)DM*DDIM];
__device__ float          g_ss[DN];
__device__ float          g_so[DM];
__device__ unsigned       g_mx[DN];

// ---------------- fp32 -> (hi,lo) bf16 split ---------------------------------
__device__ __forceinline__ void split_wr(bf16* H, bf16* L, float4 v) {
    bf16 h0 = __float2bfloat16(v.x), h1 = __float2bfloat16(v.y);
    bf16 h2 = __float2bfloat16(v.z), h3 = __float2bfloat16(v.w);
    bf16 l0 = __float2bfloat16(v.x - __bfloat162float(h0));
    bf16 l1 = __float2bfloat16(v.y - __bfloat162float(h1));
    bf16 l2 = __float2bfloat16(v.z - __bfloat162float(h2));
    bf16 l3 = __float2bfloat16(v.w - __bfloat162float(h3));
    ((__nv_bfloat162*)H)[0] = __halves2bfloat162(h0, h1);
    ((__nv_bfloat162*)H)[1] = __halves2bfloat162(h2, h3);
    ((__nv_bfloat162*)L)[0] = __halves2bfloat162(l0, l1);
    ((__nv_bfloat162*)L)[1] = __halves2bfloat162(l2, l3);
}

__global__ void ksplit(const float* __restrict__ x, bf16* __restrict__ hi,
                       bf16* __restrict__ lo, int n4) {
    int i = blockIdx.x * 256 + threadIdx.x;
    if (i < n4)
        split_wr(hi + 4 * (size_t)i, lo + 4 * (size_t)i, ((const float4*)x)[i]);
}

// all six 256x256 weights in one launch: 6*16384 float4 elements
__global__ void ksplit6(const float* w0, const float* w1, const float* w2,
                        const float* w3, const float* w4, const float* w5,
                        bf16* __restrict__ hi, bf16* __restrict__ lo) {
    int i = blockIdx.x * 256 + threadIdx.x;   // 0 .. 98303
    int which = i >> 14, off = i & 16383;
    const float* w = (which == 0) ? w0 : (which == 1) ? w1 : (which == 2) ? w2
                   : (which == 3) ? w3 : (which == 4) ? w4 : w5;
    split_wr(hi + 4 * (size_t)i, lo + 4 * (size_t)i, ((const float4*)w)[off]);
}

// ---------------- mma.sync bf16 GEMM + proj, 2 CTA/SM ------------------------
// C[64,256] = proj(X@W^T); 3-term split Ahi*Bhi + Ahi*Blo + Alo*Bhi.
// Block 256 thr (8 warps), warp tile 32x64 (wm=wid&1, wn=wid>>1), K chunks 32.
// 2-stage cp.async; CTA tile 64x256 so 2 CTAs co-reside per SM (hide syncs).
// Optional fused dot: dotout[row] = C_row . dotq[dotg?dotg[row]:row].
__device__ __forceinline__ void mma16816(float* d, const unsigned* a,
                                         unsigned b0, unsigned b1) {
    asm volatile(
        "mma.sync.aligned.m16n8k16.row.col.f32.bf16.bf16.f32 "
        "{%0,%1,%2,%3}, {%4,%5,%6,%7}, {%8,%9}, {%0,%1,%2,%3};"
        : "+f"(d[0]), "+f"(d[1]), "+f"(d[2]), "+f"(d[3])
        : "r"(a[0]), "r"(a[1]), "r"(a[2]), "r"(a[3]), "r"(b0), "r"(b1));
}
__device__ __forceinline__ void ldsm4(unsigned& r0, unsigned& r1,
                                      unsigned& r2, unsigned& r3, uint32_t addr) {
    asm volatile("ldmatrix.sync.aligned.m8n8.x4.shared.b16 {%0,%1,%2,%3}, [%4];"
        : "=r"(r0), "=r"(r1), "=r"(r2), "=r"(r3) : "r"(addr));
}
__device__ __forceinline__ void cpa16(uint32_t dst, const void* src) {
    asm volatile("cp.async.cg.shared.global [%0], [%1], 16;"
                 :: "r"(dst), "l"(src));
}
#define CP_COMMIT() asm volatile("cp.async.commit_group;")
#define CP_WAIT1()  asm volatile("cp.async.wait_group 1;")
#define CP_WAIT0()  asm volatile("cp.async.wait_group 0;")

#define ASTR 40                 // bf16 stride: 80B rows, ldmatrix conflict-free
#define STG_BYTES 51200         // AH 5120 | AL 5120 | BH 20480 | BL 20480
#define OFF_AL 5120
#define OFF_BH 10240
#define OFF_RN (2*STG_BYTES)
#define OFF_RD (OFF_RN + 256)
#define OFF_RS (OFF_RD + 256)
#define SMEMTC (OFF_RS + 256)

__global__ void __launch_bounds__(256, 2) mma_proj_tc(
    const bf16* __restrict__ Ahi, const bf16* __restrict__ Alo,
    const int* __restrict__ gidx,
    const bf16* __restrict__ Bhi, const bf16* __restrict__ Blo,
    float* __restrict__ C, int nrows,
    const float* __restrict__ dotq, const int* __restrict__ dotg,
    float* __restrict__ dotout)
{
    extern __shared__ __align__(16) char smc[];
    float* rn   = (float*)(smc + OFF_RN);
    float* rd   = (float*)(smc + OFF_RD);
    int*   rsrc = (int*)  (smc + OFF_RS);
    uint32_t sbase = (uint32_t)__cvta_generic_to_shared(smc);

    int tid = threadIdx.x;
    int wid = tid >> 5, lane = tid & 31;
    int wm = wid & 1, wn = wid >> 1;           // wm: 2x32 rows, wn: 4x64 cols
    int g  = lane >> 2, tg = lane & 3;
    int r0 = blockIdx.x * 64;

    if (tid < 64) {
        int sr = r0 + tid;
        if (sr >= nrows) sr = nrows - 1;
        rsrc[tid] = gidx ? gidx[sr] : sr;
        rn[tid] = 0.f;
        rd[tid] = 0.f;
    }
    __syncthreads();

    // fill roles: each thread owns one 16B segment column (seg = tid&3)
    int frow = tid >> 2, seg = tid & 3;        // frow: 0..63
    size_t ab0 = (size_t)rsrc[frow] * 256 + seg * 8;
    uint32_t dA0 = sbase + frow * 80 + seg * 16;

    // ldmatrix per-lane byte offsets (80B rows)
    uint32_t aoff = (uint32_t)((((lane >> 3) & 1) * 8 + (lane & 7)) * 80
                               + (lane >> 4) * 16);
    uint32_t boff = (uint32_t)((((lane >> 3) >> 1) * 8 + (lane & 7)) * 80
                               + ((lane >> 3) & 1) * 16);

    float acc[2][8][4];
#pragma unroll
    for (int mt = 0; mt < 2; mt++)
#pragma unroll
        for (int nt = 0; nt < 8; nt++)
#pragma unroll
            for (int j = 0; j < 4; j++) acc[mt][nt][j] = 0.f;

    // prefetch chunk 0 into stage 0
    {
        cpa16(dA0, Ahi + ab0); cpa16(dA0 + OFF_AL, Alo + ab0);
#pragma unroll
        for (int e = 0; e < 4; e++) {
            int row = frow + e * 64;
            uint32_t dB = sbase + OFF_BH + row * 80 + seg * 16;
            cpa16(dB, Bhi + (size_t)row * 256 + seg * 8);
            cpa16(dB + 20480, Blo + (size_t)row * 256 + seg * 8);
        }
        CP_COMMIT();
    }

    for (int c = 0; c < 8; c++) {
        if (c < 7) {
            int k1 = (c + 1) * 32;
            uint32_t so = ((c + 1) & 1) * STG_BYTES;
            cpa16(dA0 + so, Ahi + ab0 + k1);
            cpa16(dA0 + OFF_AL + so, Alo + ab0 + k1);
#pragma unroll
            for (int e = 0; e < 4; e++) {
                int row = frow + e * 64;
                uint32_t dB = sbase + OFF_BH + row * 80 + seg * 16 + so;
                cpa16(dB, Bhi + (size_t)row * 256 + seg * 8 + k1);
                cpa16(dB + 20480, Blo + (size_t)row * 256 + seg * 8 + k1);
            }
            CP_COMMIT();
            CP_WAIT1();
        } else {
            CP_WAIT0();
        }
        __syncthreads();

        uint32_t stg = sbase + (c & 1) * STG_BYTES;
        uint32_t aH = stg + (uint32_t)(wm * 32) * 80 + aoff;           // AsH
        uint32_t aL = aH + OFF_AL;                                     // AsL
        uint32_t bH = stg + OFF_BH + (uint32_t)(wn * 64) * 80 + boff;  // BsH
        uint32_t bL = bH + 20480;                                      // BsL

#pragma unroll
        for (int ks = 0; ks < 2; ks++) {
            uint32_t kb = (uint32_t)(ks * 32);   // 16 bf16 = 32 bytes
            unsigned afH[2][4], afL[2][4];
#pragma unroll
            for (int mt = 0; mt < 2; mt++) {
                ldsm4(afH[mt][0], afH[mt][1], afH[mt][2], afH[mt][3],
                      aH + (uint32_t)(mt * 1280) + kb);
                ldsm4(afL[mt][0], afL[mt][1], afL[mt][2], afL[mt][3],
                      aL + (uint32_t)(mt * 1280) + kb);
            }
#pragma unroll
            for (int np = 0; np < 4; np++) {
                unsigned b0[4], b1[4];            // bh pair + bl pair (2 nt)
                ldsm4(b0[0], b0[1], b0[2], b0[3],
                      bH + (uint32_t)(np * 1280) + kb);
                ldsm4(b1[0], b1[1], b1[2], b1[3],
                      bL + (uint32_t)(np * 1280) + kb);
                int n0 = 2 * np, n1 = 2 * np + 1;
                // term1: Ahi*Bhi
#pragma unroll
                for (int mt = 0; mt < 2; mt++) {
                    mma16816(acc[mt][n0], afH[mt], b0[0], b0[1]);
                    mma16816(acc[mt][n1], afH[mt], b0[2], b0[3]);
                }
                // term2: Ahi*Blo
#pragma unroll
                for (int mt = 0; mt < 2; mt++) {
                    mma16816(acc[mt][n0], afH[mt], b1[0], b1[1]);
                    mma16816(acc[mt][n1], afH[mt], b1[2], b1[3]);
                }
                // term3: Alo*Bhi
#pragma unroll
                for (int mt = 0; mt < 2; mt++) {
                    mma16816(acc[mt][n0], afL[mt], b0[0], b0[1]);
                    mma16816(acc[mt][n1], afL[mt], b0[2], b0[3]);
                }
            }
        }
        __syncthreads();
    }

    // ---- projection: per-row sumsq across 256 cols via smem atomics ----
#pragma unroll
    for (int mt = 0; mt < 2; mt++) {
        float s0 = 0.f, s1 = 0.f;
#pragma unroll
        for (int nt = 0; nt < 8; nt++) {
            s0 += acc[mt][nt][0] * acc[mt][nt][0] + acc[mt][nt][1] * acc[mt][nt][1];
            s1 += acc[mt][nt][2] * acc[mt][nt][2] + acc[mt][nt][3] * acc[mt][nt][3];
        }
        s0 += __shfl_xor_sync(0xffffffffu, s0, 1);
        s0 += __shfl_xor_sync(0xffffffffu, s0, 2);
        s1 += __shfl_xor_sync(0xffffffffu, s1, 1);
        s1 += __shfl_xor_sync(0xffffffffu, s1, 2);
        if (tg == 0) {
            atomicAdd(&rn[wm * 32 + mt * 16 + g], s0);
            atomicAdd(&rn[wm * 32 + mt * 16 + 8 + g], s1);
        }
    }
    __syncthreads();

#pragma unroll
    for (int mt = 0; mt < 2; mt++) {
        int rl = wm * 32 + mt * 16 + g;
        float sa = rsqrtf(rn[rl]);
        float sb = rsqrtf(rn[rl + 8]);
        bool oka = (r0 + rl) < nrows;
        bool okb = (r0 + rl + 8) < nrows;
#pragma unroll
        for (int nt = 0; nt < 8; nt++) {
            acc[mt][nt][0] *= sa; acc[mt][nt][1] *= sa;
            acc[mt][nt][2] *= sb; acc[mt][nt][3] *= sb;
        }
        if (C) {
            float* ca = C + (size_t)(r0 + rl) * 256;
            float* cb = C + (size_t)(r0 + rl + 8) * 256;
#pragma unroll
            for (int nt = 0; nt < 8; nt++) {
                int col = wn * 64 + nt * 8 + tg * 2;
                if (oka) *(float2*)(ca + col) =
                    make_float2(acc[mt][nt][0], acc[mt][nt][1]);
                if (okb) *(float2*)(cb + col) =
                    make_float2(acc[mt][nt][2], acc[mt][nt][3]);
            }
        }
        if (dotq) {
            float da = 0.f, db = 0.f;
            if (oka) {
                int qa = dotg ? dotg[r0 + rl] : (r0 + rl);
                const float* qp = dotq + (size_t)qa * 256;
#pragma unroll
                for (int nt = 0; nt < 8; nt++) {
                    float2 q = *(const float2*)(qp + wn * 64 + nt * 8 + tg * 2);
                    da += acc[mt][nt][0] * q.x + acc[mt][nt][1] * q.y;
                }
            }
            if (okb) {
                int qb = dotg ? dotg[r0 + rl + 8] : (r0 + rl + 8);
                const float* qp = dotq + (size_t)qb * 256;
#pragma unroll
                for (int nt = 0; nt < 8; nt++) {
                    float2 q = *(const float2*)(qp + wn * 64 + nt * 8 + tg * 2);
                    db += acc[mt][nt][2] * q.x + acc[mt][nt][3] * q.y;
                }
            }
            da += __shfl_xor_sync(0xffffffffu, da, 1);
            da += __shfl_xor_sync(0xffffffffu, da, 2);
            db += __shfl_xor_sync(0xffffffffu, db, 1);
            db += __shfl_xor_sync(0xffffffffu, db, 2);
            if (tg == 0) {
                atomicAdd(&rd[rl], da);
                atomicAdd(&rd[rl + 8], db);
            }
        }
    }
    if (dotq) {
        __syncthreads();
        if (tid < 64 && (r0 + tid) < nrows) dotout[r0 + tid] = rd[tid];
    }
}

// ---------------- packed f32x2 helpers (FFMA2 path, attention) ---------------
__device__ __forceinline__ unsigned long long pack2(float x, float y) {
    unsigned long long r;
    asm("mov.b64 %0, {%1,%2};" : "=l"(r)
        : "r"(__float_as_uint(x)), "r"(__float_as_uint(y)));
    return r;
}
__device__ __forceinline__ void fma2(unsigned long long& d,
                                     unsigned long long a, unsigned long long b) {
    asm("fma.rn.f32x2 %0, %1, %2, %0;" : "+l"(d) : "l"(a), "l"(b));
}
__device__ __forceinline__ float2 unpack2(unsigned long long r) {
    unsigned lo, hi;
    asm("mov.b64 {%0,%1}, %2;" : "=r"(lo), "=r"(hi) : "l"(r));
    return make_float2(__uint_as_float(lo), __uint_as_float(hi));
}
__device__ __forceinline__ unsigned encf(float f) {
    unsigned u = __float_as_uint(f);
    return (u & 0x80000000u) ? ~u : (u | 0x80000000u);
}
__device__ __forceinline__ float decf(unsigned u) {
    return __uint_as_float((u & 0x80000000u) ? (u & 0x7fffffffu) : ~u);
}

// -------- per-group scores: E = exp(Q@K^T - rowmax) --------------------------
#define QSTR 132
#define KSTR 130

__global__ __launch_bounds__(256) void attn_scores(
    const float* __restrict__ Q, const float* __restrict__ K, float* __restrict__ E)
{
    __shared__ float Qs[32 * QSTR];
    __shared__ float Ks[32 * KSTR];
    __shared__ float pm[128 * 17];

    int tid = threadIdx.x;
    int lane = tid & 31;
    int w = tid >> 5;
    int rg = w * 2 + (lane >> 4);
    int lc = lane & 15;
    int g = blockIdx.x;
    const float* Qg = Q + (size_t)g * 128 * 256;
    const float* Kg = K + (size_t)g * 128 * 256;

    unsigned long long acc[8][4];
#pragma unroll
    for (int i = 0; i < 8; i++) { acc[i][0]=0ULL; acc[i][1]=0ULL; acc[i][2]=0ULL; acc[i][3]=0ULL; }

    for (int k0 = 0; k0 < 256; k0 += 32) {
#pragma unroll
        for (int e = 0; e < 4; e++) {
            int idx = tid + e * 256;
            int row = idx >> 3, qq = idx & 7;
            float4 v = *(const float4*)(Qg + (size_t)row * 256 + (k0 + qq * 4));
            Qs[(qq*4+0)*QSTR + row] = v.x; Qs[(qq*4+1)*QSTR + row] = v.y;
            Qs[(qq*4+2)*QSTR + row] = v.z; Qs[(qq*4+3)*QSTR + row] = v.w;
            float4 u = *(const float4*)(Kg + (size_t)row * 256 + (k0 + qq * 4));
            Ks[(qq*4+0)*KSTR + row] = u.x; Ks[(qq*4+1)*KSTR + row] = u.y;
            Ks[(qq*4+2)*KSTR + row] = u.z; Ks[(qq*4+3)*KSTR + row] = u.w;
        }
        __syncthreads();
#pragma unroll
        for (int kk = 0; kk < 32; kk++) {
            float4 xa = *(const float4*)(Qs + kk * QSTR + rg * 8);
            float4 xb = *(const float4*)(Qs + kk * QSTR + rg * 8 + 4);
            const unsigned long long* wp = (const unsigned long long*)(Ks + kk * KSTR);
            unsigned long long b0 = wp[lc*2],      b1 = wp[lc*2 + 1];
            unsigned long long b2 = wp[32 + lc*2], b3 = wp[32 + lc*2 + 1];
            float xs8[8] = {xa.x, xa.y, xa.z, xa.w, xb.x, xb.y, xb.z, xb.w};
#pragma unroll
            for (int i = 0; i < 8; i++) {
                unsigned long long a = pack2(xs8[i], xs8[i]);
                fma2(acc[i][0], a, b0); fma2(acc[i][1], a, b1);
                fma2(acc[i][2], a, b2); fma2(acc[i][3], a, b3);
            }
        }
        __syncthreads();
    }

    float c[8][8];
    int rb = rg * 8;
#pragma unroll
    for (int i = 0; i < 8; i++) {
        float2 p0 = unpack2(acc[i][0]), p1 = unpack2(acc[i][1]);
        float2 p2 = unpack2(acc[i][2]), p3 = unpack2(acc[i][3]);
        c[i][0]=p0.x; c[i][1]=p0.y; c[i][2]=p1.x; c[i][3]=p1.y;
        c[i][4]=p2.x; c[i][5]=p2.y; c[i][6]=p3.x; c[i][7]=p3.y;
        float m = c[i][0];
#pragma unroll
        for (int j = 1; j < 8; j++) m = fmaxf(m, c[i][j]);
        pm[(rb + i) * 17 + lc] = m;
    }
    __syncthreads();
#pragma unroll
    for (int i = 0; i < 8; i++) {
        float m = pm[(rb + i) * 17];
#pragma unroll
        for (int t = 1; t < 16; t++) m = fmaxf(m, pm[(rb + i) * 17 + t]);
        size_t base = (size_t)g * 16384 + (size_t)(rb + i) * 128;
        *(float4*)(E + base + lc * 4) = make_float4(
            __expf(c[i][0]-m), __expf(c[i][1]-m), __expf(c[i][2]-m), __expf(c[i][3]-m));
        *(float4*)(E + base + 64 + lc * 4) = make_float4(
            __expf(c[i][4]-m), __expf(c[i][5]-m), __expf(c[i][6]-m), __expf(c[i][7]-m));
    }
}

// -------- per-group apply: att_half = E @ V_half -> split bf16 out -----------
#define ESTR 132
#define VSTR 132

__global__ __launch_bounds__(256) void attn_apply(
    const float* __restrict__ E, const float* __restrict__ V,
    bf16* __restrict__ Oh, bf16* __restrict__ Ol)
{
    __shared__ float Es[32 * ESTR];
    __shared__ float Vs[32 * VSTR];

    int tid = threadIdx.x;
    int lane = tid & 31;
    int w = tid >> 5;
    int rg = w * 2 + (lane >> 4);
    int lc = lane & 15;
    int g = blockIdx.x >> 1, half = blockIdx.x & 1;
    const float* Eg = E + (size_t)g * 16384;
    const float* Vg = V + (size_t)g * 128 * 256 + half * 128;

    unsigned long long acc[8][4];
#pragma unroll
    for (int i = 0; i < 8; i++) { acc[i][0]=0ULL; acc[i][1]=0ULL; acc[i][2]=0ULL; acc[i][3]=0ULL; }

    for (int k0 = 0; k0 < 128; k0 += 32) {
#pragma unroll
        for (int e = 0; e < 4; e++) {
            int idx = tid + e * 256;
            int row = idx >> 3, qq = idx & 7;
            float4 v = *(const float4*)(Eg + (size_t)row * 128 + (k0 + qq * 4));
            Es[(qq*4+0)*ESTR + row] = v.x; Es[(qq*4+1)*ESTR + row] = v.y;
            Es[(qq*4+2)*ESTR + row] = v.z; Es[(qq*4+3)*ESTR + row] = v.w;
            int kk = idx >> 5, cv = idx & 31;
            float4 u = *(const float4*)(Vg + (size_t)(k0 + kk) * 256 + cv * 4);
            *(float4*)(Vs + kk * VSTR + cv * 4) = u;
        }
        __syncthreads();
#pragma unroll
        for (int kk = 0; kk < 32; kk++) {
            float4 xa = *(const float4*)(Es + kk * ESTR + rg * 8);
            float4 xb = *(const float4*)(Es + kk * ESTR + rg * 8 + 4);
            const unsigned long long* wp = (const unsigned long long*)(Vs + kk * VSTR);
            unsigned long long b0 = wp[lc*2],      b1 = wp[lc*2 + 1];
            unsigned long long b2 = wp[32 + lc*2], b3 = wp[32 + lc*2 + 1];
            float xs8[8] = {xa.x, xa.y, xa.z, xa.w, xb.x, xb.y, xb.z, xb.w};
#pragma unroll
            for (int i = 0; i < 8; i++) {
                unsigned long long a = pack2(xs8[i], xs8[i]);
                fma2(acc[i][0], a, b0); fma2(acc[i][1], a, b1);
                fma2(acc[i][2], a, b2); fma2(acc[i][3], a, b3);
            }
        }
        __syncthreads();
    }

    int rb = rg * 8;
#pragma unroll
    for (int i = 0; i < 8; i++) {
        float2 p0 = unpack2(acc[i][0]), p1 = unpack2(acc[i][1]);
        float2 p2 = unpack2(acc[i][2]), p3 = unpack2(acc[i][3]);
        size_t base = (size_t)(g * 128 + rb + i) * 256 + half * 128;
        split_wr(Oh + base + lc * 4,      Ol + base + lc * 4,
                 make_float4(p0.x, p0.y, p1.x, p1.y));
        split_wr(Oh + base + 64 + lc * 4, Ol + base + 64 + lc * 4,
                 make_float4(p2.x, p2.y, p3.x, p3.y));
    }
}

// ---------------- segment phase ---------------------------------------------
__global__ void kinit_max(const float* __restrict__ ss, unsigned* __restrict__ mx, int n)
{
    int i = blockIdx.x * 256 + threadIdx.x;
    if (i < n) mx[i] = encf(ss[i]);
}

__global__ void kseg_max(const float* __restrict__ so, const int* __restrict__ seg,
                         unsigned* __restrict__ mx)
{
    int i = blockIdx.x * 256 + threadIdx.x;
    atomicMax(&mx[seg[i]], encf(so[i]));
}

__global__ void kout_init(const float* __restrict__ ss, const unsigned* __restrict__ mx,
                          const float* __restrict__ vs, float* __restrict__ out)
{
    int t = blockIdx.x * 256 + threadIdx.x;
    int i = t >> 6, j = t & 63;
    float e = __expf(ss[i] - decf(mx[i]));
    float4 v = ((const float4*)vs)[(size_t)i * 64 + j];
    ((float4*)out)[(size_t)i * 64 + j] = make_float4(e*v.x, e*v.y, e*v.z, e*v.w);
}

__global__ void kocc_acc(const float* __restrict__ so, const int* __restrict__ seg,
                         const unsigned* __restrict__ mx, const float* __restrict__ vo,
                         float* __restrict__ out)
{
    int t = blockIdx.x * 256 + threadIdx.x;
    int i = t >> 6, j = t & 63;
    int n = seg[i];
    float e = __expf(so[i] - decf(mx[n]));
    float4 v = ((const float4*)vo)[(size_t)i * 64 + j];
    float* p = out + (size_t)n * 256 + j * 4;
    asm volatile("red.global.add.v4.f32 [%0], {%1, %2, %3, %4};"
                 :: "l"(p), "f"(e * v.x), "f"(e * v.y), "f"(e * v.z), "f"(e * v.w)
                 : "memory");
}

__global__ void knorm(float* __restrict__ out)
{
    int row = blockIdx.x * 8 + (threadIdx.x >> 5);
    int lane = threadIdx.x & 31;
    float4* p = (float4*)(out + (size_t)row * 256);
    float4 a = p[lane], b = p[lane + 32];
    float s = a.x*a.x + a.y*a.y + a.z*a.z + a.w*a.w
            + b.x*b.x + b.y*b.y + b.z*b.z + b.w*b.w;
#pragma unroll
    for (int o = 16; o; o >>= 1) s += __shfl_xor_sync(0xffffffffu, s, o);
    float r = rsqrtf(s);
    p[lane]      = make_float4(a.x*r, a.y*r, a.z*r, a.w*r);
    p[lane + 32] = make_float4(b.x*r, b.y*r, b.z*r, b.w*r);
}

// ---------------- launch -----------------------------------------------------
extern "C" void kernel_launch(void* const* d_in, const int* in_sizes, int n_in,
                              void* d_out, int out_size)
{
    const float* xS  = (const float*)d_in[0];
    const int*   sub = (const int*)  d_in[1];
    const float* W0 = (const float*)d_in[2];
    const float* W1 = (const float*)d_in[3];
    const float* W2 = (const float*)d_in[4];
    const float* W3 = (const float*)d_in[5];
    const float* W4 = (const float*)d_in[6];
    const float* W5 = (const float*)d_in[7];
    float* out = (float*)d_out;

    float *q1, *k1, *v1, *E, *q2, *vs, *vo, *ss, *so;
    unsigned short *ath, *atl, *xh, *xl, *wh, *wl;
    unsigned* mx;
    cudaGetSymbolAddress((void**)&q1,  g_q1);
    cudaGetSymbolAddress((void**)&k1,  g_k1);
    cudaGetSymbolAddress((void**)&v1,  g_v1);
    cudaGetSymbolAddress((void**)&E,   g_E);
    cudaGetSymbolAddress((void**)&ath, g_ath);
    cudaGetSymbolAddress((void**)&atl, g_atl);
    cudaGetSymbolAddress((void**)&xh,  g_xh);
    cudaGetSymbolAddress((void**)&xl,  g_xl);
    cudaGetSymbolAddress((void**)&wh,  g_wh);
    cudaGetSymbolAddress((void**)&wl,  g_wl);
    cudaGetSymbolAddress((void**)&q2,  g_q2);
    cudaGetSymbolAddress((void**)&vs,  g_vs);
    cudaGetSymbolAddress((void**)&vo,  g_vo);
    cudaGetSymbolAddress((void**)&ss,  g_ss);
    cudaGetSymbolAddress((void**)&so,  g_so);
    cudaGetSymbolAddress((void**)&mx,  g_mx);

    cudaFuncSetAttribute(mma_proj_tc, cudaFuncAttributeMaxDynamicSharedMemorySize, SMEMTC);

    bf16* XH = (bf16*)xh;  bf16* XL = (bf16*)xl;
    bf16* AH = (bf16*)ath; bf16* AL = (bf16*)atl;
    bf16* WH[6]; bf16* WL[6];
    for (int i = 0; i < 6; i++) { WH[i] = (bf16*)(wh + i * 65536); WL[i] = (bf16*)(wl + i * 65536); }

    int nTilesM = DM / 64;             // 2048
    int nTilesN = DN / 64;             // 3125 (exact)

    // #1, #2: input splits
    ksplit<<<DN * 64 / 256, 256>>>(xS, XH, XL, DN * 64);
    ksplit6<<<384, 256>>>(W0, W1, W2, W3, W4, W5, WH[0], WL[0]);

    // #3-#5: phase-1 projections (gathered)
    mma_proj_tc<<<nTilesM, 256, SMEMTC>>>(XH, XL, sub, WH[0], WL[0], q1, DM,
                                          nullptr, nullptr, nullptr);
    mma_proj_tc<<<nTilesM, 256, SMEMTC>>>(XH, XL, sub, WH[1], WL[1], k1, DM,
                                          nullptr, nullptr, nullptr);
    mma_proj_tc<<<nTilesM, 256, SMEMTC>>>(XH, XL, sub, WH[2], WL[2], v1, DM,
                                          nullptr, nullptr, nullptr);

    // #6-#8: phase-2 X projections (independent of attention; #6 gets profiled)
    mma_proj_tc<<<nTilesN, 256, SMEMTC>>>(XH, XL, nullptr, WH[3], WL[3], q2, DN,
                                          nullptr, nullptr, nullptr);
    mma_proj_tc<<<nTilesN, 256, SMEMTC>>>(XH, XL, nullptr, WH[5], WL[5], vs, DN,
                                          nullptr, nullptr, nullptr);
    mma_proj_tc<<<nTilesN, 256, SMEMTC>>>(XH, XL, nullptr, WH[4], WL[4],
                                          nullptr, DN, q2, nullptr, ss);

    // #9-#10: subset attention
    attn_scores<<<DG, 256>>>(q1, k1, E);
    attn_apply<<<DG * 2, 256>>>(E, v1, AH, AL);

    // #11-#12: att projections (dot-fused ko, plus vo)
    mma_proj_tc<<<nTilesM, 256, SMEMTC>>>(AH, AL, nullptr, WH[4], WL[4],
                                          nullptr, DM, q2, sub, so);
    mma_proj_tc<<<nTilesM, 256, SMEMTC>>>(AH, AL, nullptr, WH[5], WL[5], vo, DM,
                                          nullptr, nullptr, nullptr);

    // segment softmax aggregation
    kinit_max<<<(DN + 255) / 256, 256>>>(ss, mx, DN);
    kseg_max<<<DM / 256, 256>>>(so, sub, mx);
    kout_init<<<DN * 64 / 256, 256>>>(ss, mx, vs, out);
    kocc_acc<<<DM * 64 / 256, 256>>>(so, sub, mx, vo, out);
    knorm<<<DN / 8, 256>>>(out);
}